// round 12
// baseline (speedup 1.0000x reference)
#include <cuda_runtime.h>
#include <cuda_bf16.h>
#include <math.h>
#include <cstdint>

// Problem constants
#define B_    8
#define KTOK  512
#define C_    256
#define HEADS 8
#define DH    32
#define NS    64
#define FF_   1024
#define NT    (B_*KTOK)   // 4096 tokens

// ---------------- scratch (device globals; no allocation allowed) ----------
__device__ float d_y [NT*C_];
__device__ float d_x [NT*C_];

__device__ __nv_bfloat16 d_wqh[C_*C_],  d_wql[C_*C_];
__device__ __nv_bfloat16 d_wvh[C_*C_],  d_wvl[C_*C_];
__device__ __nv_bfloat16 d_woh[C_*C_],  d_wol[C_*C_];
__device__ __nv_bfloat16 d_w1h[C_*FF_], d_w1l[C_*FF_];
__device__ __nv_bfloat16 d_w2h[FF_*C_], d_w2l[FF_*C_];
__device__ __nv_bfloat16 d_wkth[C_*C_], d_wktl[C_*C_];   // scale * Wk^T
__device__ __nv_bfloat16 d_qh [NT*C_],  d_ql [NT*C_];    // query
__device__ __nv_bfloat16 d_qph[NT*C_],  d_qpl[NT*C_];    // q projection
__device__ __nv_bfloat16 d_qkh[NT*HEADS*C_], d_qkl[NT*HEADS*C_];
__device__ __nv_bfloat16 d_gh [NT*HEADS*C_], d_gl [NT*HEADS*C_];
__device__ __nv_bfloat16 d_ch [NT*C_],  d_cl [NT*C_];
__device__ __nv_bfloat16 d_xh [NT*C_],  d_xl [NT*C_];
__device__ __nv_bfloat16 d_h1h[NT*FF_], d_h1l[NT*FF_];

__device__ __forceinline__ float gelu_tanh(float x) {
    float x3 = x*x*x;
    return 0.5f*x*(1.f + tanhf(0.7978845608028654f*(x + 0.044715f*x3)));
}

__device__ __forceinline__ uint32_t smem_u32(const void* p) {
    uint32_t a;
    asm("{ .reg .u64 t; cvta.to.shared.u64 t, %1; cvt.u32.u64 %0, t; }" : "=r"(a) : "l"(p));
    return a;
}

// ---- ldmatrix / mma.sync / cp.async wrappers (arch-agnostic, sm_80+) -------
__device__ __forceinline__ void ldsm_x4(uint32_t (&r)[4], uint32_t addr) {
    asm volatile("ldmatrix.sync.aligned.m8n8.x4.shared.b16 {%0,%1,%2,%3}, [%4];"
        : "=r"(r[0]), "=r"(r[1]), "=r"(r[2]), "=r"(r[3]) : "r"(addr));
}
__device__ __forceinline__ void ldsm_x4_t(uint32_t (&r)[4], uint32_t addr) {
    asm volatile("ldmatrix.sync.aligned.m8n8.x4.trans.shared.b16 {%0,%1,%2,%3}, [%4];"
        : "=r"(r[0]), "=r"(r[1]), "=r"(r[2]), "=r"(r[3]) : "r"(addr));
}
__device__ __forceinline__ void ldsm_x2(uint32_t (&r)[2], uint32_t addr) {
    asm volatile("ldmatrix.sync.aligned.m8n8.x2.shared.b16 {%0,%1}, [%2];"
        : "=r"(r[0]), "=r"(r[1]) : "r"(addr));
}
__device__ __forceinline__ void ldsm_x2_t(uint32_t (&r)[2], uint32_t addr) {
    asm volatile("ldmatrix.sync.aligned.m8n8.x2.trans.shared.b16 {%0,%1}, [%2];"
        : "=r"(r[0]), "=r"(r[1]) : "r"(addr));
}
__device__ __forceinline__ void mma_bf16(float (&d)[4], const uint32_t (&a)[4],
                                         uint32_t b0, uint32_t b1) {
    asm volatile(
        "mma.sync.aligned.m16n8k16.row.col.f32.bf16.bf16.f32 "
        "{%0,%1,%2,%3}, {%4,%5,%6,%7}, {%8,%9}, {%0,%1,%2,%3};"
        : "+f"(d[0]), "+f"(d[1]), "+f"(d[2]), "+f"(d[3])
        : "r"(a[0]), "r"(a[1]), "r"(a[2]), "r"(a[3]), "r"(b0), "r"(b1));
}
__device__ __forceinline__ void cp16(uint32_t dst, const void* src) {
    asm volatile("cp.async.cg.shared.global [%0], [%1], 16;" :: "r"(dst), "l"(src));
}
#define CP_COMMIT() asm volatile("cp.async.commit_group;" ::: "memory")
#define CP_WAIT(n)  asm volatile("cp.async.wait_group %0;" :: "n"(n) : "memory")

// round-to-nearest hi/lo split (weights, outputs)
__device__ __forceinline__ void split2(float x, float y, uint32_t& h, uint32_t& l) {
    __nv_bfloat162 hh = __floats2bfloat162_rn(x, y);
    float rx = x - __bfloat162float(hh.x);
    float ry = y - __bfloat162float(hh.y);
    __nv_bfloat162 ll = __floats2bfloat162_rn(rx, ry);
    h = *(uint32_t*)&hh;  l = *(uint32_t*)&ll;
}
// truncation hi/lo split (cheaper; residual <= 2^-17 rel) — attn feats hot path
__device__ __forceinline__ void split2t(float x, float y, uint32_t& h, uint32_t& l) {
    uint32_t bx = __float_as_uint(x), by = __float_as_uint(y);
    h = (bx >> 16) | (by & 0xFFFF0000u);
    float lx = x - __uint_as_float(bx & 0xFFFF0000u);
    float ly = y - __uint_as_float(by & 0xFFFF0000u);
    __nv_bfloat162 ll = __floats2bfloat162_rn(lx, ly);
    l = *(uint32_t*)&ll;
}

// ---------------- conversion kernels ------------------------------------
__device__ __forceinline__ void seg_split(const float* __restrict__ in,
                                          __nv_bfloat16* __restrict__ oh,
                                          __nv_bfloat16* __restrict__ ol,
                                          int blk, int tid)
{
    int i = blk*256 + tid;
    float4 v = ((const float4*)in)[i];
    uint32_t h0, l0, h1, l1;
    split2(v.x, v.y, h0, l0);
    split2(v.z, v.w, h1, l1);
    ((uint2*)oh)[i] = make_uint2(h0, h1);
    ((uint2*)ol)[i] = make_uint2(l0, l1);
}

__global__ void conv_w(const float* __restrict__ Wq, const float* __restrict__ Wv,
                       const float* __restrict__ Wo, const float* __restrict__ W1,
                       const float* __restrict__ W2,
                       __nv_bfloat16* wqh, __nv_bfloat16* wql,
                       __nv_bfloat16* wvh, __nv_bfloat16* wvl,
                       __nv_bfloat16* woh, __nv_bfloat16* wol,
                       __nv_bfloat16* w1h, __nv_bfloat16* w1l,
                       __nv_bfloat16* w2h, __nv_bfloat16* w2l)
{
    const int bid = blockIdx.x, tid = threadIdx.x;
    if      (bid < 64)  seg_split(Wq, wqh, wql, bid, tid);
    else if (bid < 128) seg_split(Wv, wvh, wvl, bid - 64, tid);
    else if (bid < 192) seg_split(Wo, woh, wol, bid - 128, tid);
    else if (bid < 448) seg_split(W1, w1h, w1l, bid - 192, tid);
    else                seg_split(W2, w2h, w2l, bid - 448, tid);
}

__global__ void conv_q(const float* __restrict__ query,
                       __nv_bfloat16* qh, __nv_bfloat16* ql)
{
    seg_split(query, qh, ql, blockIdx.x, threadIdx.x);
}

__global__ void conv_wkt(const float* __restrict__ Wk,
                         __nv_bfloat16* wkth, __nv_bfloat16* wktl)
{
    __shared__ float ts[64][65];
    const int t = blockIdx.x, tid = threadIdx.x;
    const int tc = (t >> 2)*64, td = (t & 3)*64;
    #pragma unroll
    for (int j = 0; j < 4; j++) {
        int idx = tid + 256*j;
        int r = idx >> 4, q = idx & 15;
        float4 v = *(const float4*)&Wk[(size_t)(tc + r)*C_ + td + q*4];
        ts[r][q*4+0] = v.x; ts[r][q*4+1] = v.y;
        ts[r][q*4+2] = v.z; ts[r][q*4+3] = v.w;
    }
    __syncthreads();
    const float scale = 0.17677669529663687f;   // 1/sqrt(32)
    #pragma unroll
    for (int j = 0; j < 4; j++) {
        int idx = tid + 256*j;
        int r2 = idx >> 4, q2 = idx & 15;
        float v0 = ts[q2*4+0][r2]*scale, v1 = ts[q2*4+1][r2]*scale;
        float v2 = ts[q2*4+2][r2]*scale, v3 = ts[q2*4+3][r2]*scale;
        uint32_t h0, l0, h1, l1;
        split2(v0, v1, h0, l0);
        split2(v2, v3, h1, l1);
        size_t e = (size_t)(td + r2)*C_ + tc + q2*4;
        *(uint2*)&wkth[e] = make_uint2(h0, h1);
        *(uint2*)&wktl[e] = make_uint2(l0, l1);
    }
}

// ======= bf16 hi/lo tensor-core GEMM, M128 tile (kept for qk) ===============
template<int TN, int S, bool BIAS, bool RES, bool GELU, bool OF32, bool OHL>
__global__ __launch_bounds__(256, 2)
void mma_gemm(const __nv_bfloat16* __restrict__ Ah, const __nv_bfloat16* __restrict__ Al,
              int lda,
              const __nv_bfloat16* __restrict__ Bh, const __nv_bfloat16* __restrict__ Bl,
              int ldw,
              const float* __restrict__ bias, const float* __restrict__ res,
              float* __restrict__ Out, __nv_bfloat16* __restrict__ OutH,
              __nv_bfloat16* __restrict__ OutL,
              int ldo, int K, int za, int zw, int zb, int zo)
{
    constexpr int AROW   = 80;
    constexpr int BROW   = TN*2 + 16;
    constexpr int A_BYTES = 128*AROW;
    constexpr int B_BYTES = 32*BROW;
    constexpr int STAGE  = 2*A_BYTES + 2*B_BYTES;
    constexpr int NB16   = TN/32;
    constexpr int BCH    = TN/8;
    constexpr int BCHT   = 32*BCH;

    extern __shared__ char smem[];
    const uint32_t sb = smem_u32(smem);
    const int tid  = threadIdx.x;
    const int lane = tid & 31, wid = tid >> 5;
    const int wm = wid & 3, wn = wid >> 2;
    const int m0 = blockIdx.y*128, n0 = blockIdx.x*TN;
    const int z = blockIdx.z;
    Ah += (size_t)z*za;  Al += (size_t)z*za;
    Bh += (size_t)z*zw;  Bl += (size_t)z*zw;
    if (OF32) Out += (size_t)z*zo;
    if (OHL) { OutH += (size_t)z*zo; OutL += (size_t)z*zo; }
    if (BIAS) bias += (size_t)z*zb;
    if (RES)  res  += (size_t)z*zo;

    float acc[2][NB16*2][4];
    #pragma unroll
    for (int a = 0; a < 2; a++)
        #pragma unroll
        for (int b = 0; b < NB16*2; b++)
            #pragma unroll
            for (int c = 0; c < 4; c++) acc[a][b][c] = 0.f;

    auto issue = [&](int chunk, int s) {
        const uint32_t sa = sb + s*STAGE;
        const int kc = chunk*32;
        #pragma unroll
        for (int j = 0; j < 2; j++) {
            int idx = tid + 256*j;
            int row = idx >> 2, ch = idx & 3;
            size_t soff = (size_t)(m0 + row)*lda + kc + ch*8;
            uint32_t d = sa + row*AROW + ch*16;
            cp16(d,           Ah + soff);
            cp16(d + A_BYTES, Al + soff);
        }
        if (BCHT >= 256) {
            #pragma unroll
            for (int j = 0; j < BCHT/256; j++) {
                int idx = tid + 256*j;
                int row = idx / BCH, ch = idx % BCH;
                size_t soff = (size_t)(kc + row)*ldw + n0 + ch*8;
                uint32_t d = sa + 2*A_BYTES + row*BROW + ch*16;
                cp16(d,           Bh + soff);
                cp16(d + B_BYTES, Bl + soff);
            }
        } else {
            if (tid < BCHT) {
                int row = tid / BCH, ch = tid % BCH;
                size_t soff = (size_t)(kc + row)*ldw + n0 + ch*8;
                uint32_t d = sa + 2*A_BYTES + row*BROW + ch*16;
                cp16(d,           Bh + soff);
                cp16(d + B_BYTES, Bl + soff);
            }
        }
    };
    auto compute = [&](int s) {
        const uint32_t a_h = sb + s*STAGE;
        const uint32_t a_l = a_h + A_BYTES;
        const uint32_t b_h = a_h + 2*A_BYTES;
        const uint32_t b_l = b_h + B_BYTES;
        const int l15 = lane & 15, l16 = lane >> 4;
        #pragma unroll
        for (int k16 = 0; k16 < 2; k16++) {
            uint32_t ah[2][4], al[2][4];
            #pragma unroll
            for (int mt = 0; mt < 2; mt++) {
                uint32_t aoff = (uint32_t)((wm*32 + mt*16 + l15)*AROW + k16*32 + l16*16);
                ldsm_x4(ah[mt], a_h + aoff);
                ldsm_x4(al[mt], a_l + aoff);
            }
            #pragma unroll
            for (int nb = 0; nb < NB16; nb++) {
                uint32_t boff = (uint32_t)((k16*16 + l15)*BROW + (wn*(TN/2) + nb*16)*2 + l16*16);
                uint32_t bh[4], bl[4];
                ldsm_x4_t(bh, b_h + boff);
                ldsm_x4_t(bl, b_l + boff);
                #pragma unroll
                for (int mt = 0; mt < 2; mt++) {
                    mma_bf16(acc[mt][nb*2],   ah[mt], bh[0], bh[1]);
                    mma_bf16(acc[mt][nb*2],   ah[mt], bl[0], bl[1]);
                    mma_bf16(acc[mt][nb*2],   al[mt], bh[0], bh[1]);
                    mma_bf16(acc[mt][nb*2+1], ah[mt], bh[2], bh[3]);
                    mma_bf16(acc[mt][nb*2+1], ah[mt], bl[2], bl[3]);
                    mma_bf16(acc[mt][nb*2+1], al[mt], bh[2], bh[3]);
                }
            }
        }
    };

    const int NC = K/32;
    #pragma unroll
    for (int s = 0; s < S - 1; s++) {
        if (s < NC) issue(s, s);
        CP_COMMIT();
    }
    for (int i = 0; i < NC; i++) {
        CP_WAIT(S - 2);
        __syncthreads();
        const int nx = i + S - 1;
        if (nx < NC) issue(nx, nx % S);
        CP_COMMIT();
        compute(i % S);
    }

    const int g = lane >> 2, tg = lane & 3;
    #pragma unroll
    for (int mt = 0; mt < 2; mt++) {
        const int r0 = m0 + wm*32 + mt*16 + g;
        #pragma unroll
        for (int j = 0; j < NB16*2; j++) {
            const int col = n0 + wn*(TN/2) + j*8 + tg*2;
            float v0 = acc[mt][j][0], v1 = acc[mt][j][1];
            float v2 = acc[mt][j][2], v3 = acc[mt][j][3];
            if (BIAS) {
                float b0 = bias[col], b1 = bias[col+1];
                v0 += b0; v1 += b1; v2 += b0; v3 += b1;
            }
            if (RES) {
                const float* rp0 = &res[(size_t)r0*ldo + col];
                const float* rp1 = &res[(size_t)(r0+8)*ldo + col];
                v0 += rp0[0]; v1 += rp0[1]; v2 += rp1[0]; v3 += rp1[1];
            }
            if (GELU) { v0 = gelu_tanh(v0); v1 = gelu_tanh(v1);
                        v2 = gelu_tanh(v2); v3 = gelu_tanh(v3); }
            if (OF32) {
                *(float2*)&Out[(size_t)r0*ldo + col]     = make_float2(v0, v1);
                *(float2*)&Out[(size_t)(r0+8)*ldo + col] = make_float2(v2, v3);
            }
            if (OHL) {
                uint32_t h0, l0, h1, l1;
                split2(v0, v1, h0, l0);
                split2(v2, v3, h1, l1);
                *(uint32_t*)&OutH[(size_t)r0*ldo + col]     = h0;
                *(uint32_t*)&OutL[(size_t)r0*ldo + col]     = l0;
                *(uint32_t*)&OutH[(size_t)(r0+8)*ldo + col] = h1;
                *(uint32_t*)&OutL[(size_t)(r0+8)*ldo + col] = l1;
            }
        }
    }
}

// ======= bf16 hi/lo tensor-core GEMM, M64 tile (grid-doubling variant) ======
// 8 warps as 2m x 4n; warp tile 32 x TN/4. TN in {32, 64}.
template<int TN, int S, bool BIAS, bool RES, bool GELU, bool OF32, bool OHL>
__global__ __launch_bounds__(256, 3)
void mma_gemm64(const __nv_bfloat16* __restrict__ Ah, const __nv_bfloat16* __restrict__ Al,
                int lda,
                const __nv_bfloat16* __restrict__ Bh, const __nv_bfloat16* __restrict__ Bl,
                int ldw,
                const float* __restrict__ bias, const float* __restrict__ res,
                float* __restrict__ Out, __nv_bfloat16* __restrict__ OutH,
                __nv_bfloat16* __restrict__ OutL,
                int ldo, int K, int za, int zw, int zb, int zo)
{
    constexpr int AROW   = 80;
    constexpr int BROW   = TN*2 + 16;
    constexpr int A_BYTES = 64*AROW;
    constexpr int B_BYTES = 32*BROW;
    constexpr int STAGE  = 2*A_BYTES + 2*B_BYTES;
    constexpr int NBW    = TN/4;          // per-warp n width: 8 or 16
    constexpr int NB8    = NBW/8;         // 1 or 2
    constexpr int BCH    = TN/8;
    constexpr int BCHT   = 32*BCH;        // 128 or 256

    extern __shared__ char smem[];
    const uint32_t sb = smem_u32(smem);
    const int tid  = threadIdx.x;
    const int lane = tid & 31, wid = tid >> 5;
    const int wm = wid & 1, wn = wid >> 1;
    const int m0 = blockIdx.y*64, n0 = blockIdx.x*TN;
    const int z = blockIdx.z;
    Ah += (size_t)z*za;  Al += (size_t)z*za;
    Bh += (size_t)z*zw;  Bl += (size_t)z*zw;
    if (OF32) Out += (size_t)z*zo;
    if (OHL) { OutH += (size_t)z*zo; OutL += (size_t)z*zo; }
    if (BIAS) bias += (size_t)z*zb;
    if (RES)  res  += (size_t)z*zo;

    float acc[2][NB8][4];
    #pragma unroll
    for (int a = 0; a < 2; a++)
        #pragma unroll
        for (int b = 0; b < NB8; b++)
            #pragma unroll
            for (int c = 0; c < 4; c++) acc[a][b][c] = 0.f;

    auto issue = [&](int chunk, int s) {
        const uint32_t sa = sb + s*STAGE;
        const int kc = chunk*32;
        {   // A: 64 rows x 4 chunks = 256 cp16 per array (1 per thread)
            int row = tid >> 2, ch = tid & 3;
            size_t soff = (size_t)(m0 + row)*lda + kc + ch*8;
            uint32_t d = sa + row*AROW + ch*16;
            cp16(d,           Ah + soff);
            cp16(d + A_BYTES, Al + soff);
        }
        if (BCHT >= 256) {
            int row = tid / BCH, ch = tid % BCH;
            size_t soff = (size_t)(kc + row)*ldw + n0 + ch*8;
            uint32_t d = sa + 2*A_BYTES + row*BROW + ch*16;
            cp16(d,           Bh + soff);
            cp16(d + B_BYTES, Bl + soff);
        } else {
            if (tid < BCHT) {
                int row = tid / BCH, ch = tid % BCH;
                size_t soff = (size_t)(kc + row)*ldw + n0 + ch*8;
                uint32_t d = sa + 2*A_BYTES + row*BROW + ch*16;
                cp16(d,           Bh + soff);
                cp16(d + B_BYTES, Bl + soff);
            }
        }
    };
    auto compute = [&](int s) {
        const uint32_t a_h = sb + s*STAGE;
        const uint32_t a_l = a_h + A_BYTES;
        const uint32_t b_h = a_h + 2*A_BYTES;
        const uint32_t b_l = b_h + B_BYTES;
        const int l15 = lane & 15, l16 = lane >> 4;
        #pragma unroll
        for (int k16 = 0; k16 < 2; k16++) {
            uint32_t ah[2][4], al[2][4];
            #pragma unroll
            for (int mt = 0; mt < 2; mt++) {
                uint32_t aoff = (uint32_t)((wm*32 + mt*16 + l15)*AROW + k16*32 + l16*16);
                ldsm_x4(ah[mt], a_h + aoff);
                ldsm_x4(al[mt], a_l + aoff);
            }
            if constexpr (NB8 == 2) {
                uint32_t boff = (uint32_t)((k16*16 + l15)*BROW + wn*NBW*2 + l16*16);
                uint32_t bh[4], bl[4];
                ldsm_x4_t(bh, b_h + boff);
                ldsm_x4_t(bl, b_l + boff);
                #pragma unroll
                for (int mt = 0; mt < 2; mt++) {
                    mma_bf16(acc[mt][0], ah[mt], bh[0], bh[1]);
                    mma_bf16(acc[mt][0], ah[mt], bl[0], bl[1]);
                    mma_bf16(acc[mt][0], al[mt], bh[0], bh[1]);
                    mma_bf16(acc[mt][1], ah[mt], bh[2], bh[3]);
                    mma_bf16(acc[mt][1], ah[mt], bl[2], bl[3]);
                    mma_bf16(acc[mt][1], al[mt], bh[2], bh[3]);
                }
            } else {
                uint32_t boff = (uint32_t)((k16*16 + l15)*BROW + wn*NBW*2);
                uint32_t bh[2], bl[2];
                ldsm_x2_t(bh, b_h + boff);
                ldsm_x2_t(bl, b_l + boff);
                #pragma unroll
                for (int mt = 0; mt < 2; mt++) {
                    mma_bf16(acc[mt][0], ah[mt], bh[0], bh[1]);
                    mma_bf16(acc[mt][0], ah[mt], bl[0], bl[1]);
                    mma_bf16(acc[mt][0], al[mt], bh[0], bh[1]);
                }
            }
        }
    };

    const int NC = K/32;
    #pragma unroll
    for (int s = 0; s < S - 1; s++) {
        if (s < NC) issue(s, s);
        CP_COMMIT();
    }
    for (int i = 0; i < NC; i++) {
        CP_WAIT(S - 2);
        __syncthreads();
        const int nx = i + S - 1;
        if (nx < NC) issue(nx, nx % S);
        CP_COMMIT();
        compute(i % S);
    }

    const int g = lane >> 2, tg = lane & 3;
    #pragma unroll
    for (int mt = 0; mt < 2; mt++) {
        const int r0 = m0 + wm*32 + mt*16 + g;
        #pragma unroll
        for (int j = 0; j < NB8; j++) {
            const int col = n0 + wn*NBW + j*8 + tg*2;
            float v0 = acc[mt][j][0], v1 = acc[mt][j][1];
            float v2 = acc[mt][j][2], v3 = acc[mt][j][3];
            if (BIAS) {
                float b0 = bias[col], b1 = bias[col+1];
                v0 += b0; v1 += b1; v2 += b0; v3 += b1;
            }
            if (RES) {
                const float* rp0 = &res[(size_t)r0*ldo + col];
                const float* rp1 = &res[(size_t)(r0+8)*ldo + col];
                v0 += rp0[0]; v1 += rp0[1]; v2 += rp1[0]; v3 += rp1[1];
            }
            if (GELU) { v0 = gelu_tanh(v0); v1 = gelu_tanh(v1);
                        v2 = gelu_tanh(v2); v3 = gelu_tanh(v3); }
            if (OF32) {
                *(float2*)&Out[(size_t)r0*ldo + col]     = make_float2(v0, v1);
                *(float2*)&Out[(size_t)(r0+8)*ldo + col] = make_float2(v2, v3);
            }
            if (OHL) {
                uint32_t h0, l0, h1, l1;
                split2(v0, v1, h0, l0);
                split2(v2, v3, h1, l1);
                *(uint32_t*)&OutH[(size_t)r0*ldo + col]     = h0;
                *(uint32_t*)&OutL[(size_t)r0*ldo + col]     = l0;
                *(uint32_t*)&OutH[(size_t)(r0+8)*ldo + col] = h1;
                *(uint32_t*)&OutL[(size_t)(r0+8)*ldo + col] = l1;
            }
        }
    }
}

// ---- bilinear tap of the 9x9 rel-pos table ---------------------------------
__device__ __forceinline__ float bil_corner(const float* __restrict__ th,
                                            int yi, int xi, float w)
{
    if (xi < 0 || xi > 8 || yi < 0 || yi > 8) return 0.f;
    return th[yi*9 + xi]*w;
}
__device__ __forceinline__ float grid_bias(const float* __restrict__ sp,
                                           const float* __restrict__ tab,
                                           int h, int n)
{
    float gx = (sp[2*n]   + 1.f)*4.f;
    float gy = (sp[2*n+1] + 1.f)*4.f;
    float x0f = floorf(gx), y0f = floorf(gy);
    int   x0 = (int)x0f,    y0 = (int)y0f;
    float wx1 = gx - x0f, wx0 = 1.f - wx1;
    float wy1 = gy - y0f, wy0 = 1.f - wy1;
    const float* th = &tab[h*81];
    return bil_corner(th, y0,   x0,   wy0*wx0)
         + bil_corner(th, y0,   x0+1, wy0*wx1)
         + bil_corner(th, y0+1, x0,   wy1*wx0)
         + bil_corner(th, y0+1, x0+1, wy1*wx1);
}

// ---------------- fused local attention v6 (round-10/11) --------------------
#define ASM_FH   0
#define ASM_FL   36864
#define ASM_PH   73728
#define ASM_PL   74880
#define ASM_SP   76032
#define ASM_TAB  76544
#define ASM_QH   79168
#define ASM_QL   83392
#define ASM_SCP  87616
#define ASM_GT   79168
#define ATTN_SMEM_BYTES 92736
#define FPITCH 144
#define QPITCH 528
#define PPITCH 144

__global__ __launch_bounds__(256, 2)
void attn_kernel(const float* __restrict__ lf,   const float* __restrict__ spat,
                 const float* __restrict__ table,
                 const __nv_bfloat16* __restrict__ qkh,
                 const __nv_bfloat16* __restrict__ qkl,
                 __nv_bfloat16* __restrict__ gh, __nv_bfloat16* __restrict__ gl)
{
    extern __shared__ char smem[];
    float* scp = (float*)(smem + ASM_SCP);
    float* gt  = (float*)(smem + ASM_GT);
    float* sp  = (float*)(smem + ASM_SP);
    float* tab = (float*)(smem + ASM_TAB);
    const uint32_t sb = smem_u32(smem);

    const int tid  = threadIdx.x;
    const int lane = tid & 31, w = tid >> 5;
    const int gid  = tid >> 7, lt = tid & 127;
    const int bk = blockIdx.x;
    const int b  = bk >> 9, k = bk & 511;

    const float* lfb = lf + (size_t)b*(C_*KTOK*NS) + (size_t)k*NS;
    const int v = lt & 15, cg = lt >> 4;
    float4 f[16];
    #pragma unroll
    for (int rr = 0; rr < 16; rr++) {
        int c = gid*128 + rr*8 + cg;
        f[rr] = *(const float4*)(lfb + (size_t)c*(KTOK*NS) + v*4);
    }
    {
        const uint2* qh4 = (const uint2*)(qkh + (size_t)bk*2048);
        const uint2* ql4 = (const uint2*)(qkl + (size_t)bk*2048);
        #pragma unroll
        for (int jj = 0; jj < 2; jj++) {
            int idx = lt + 128*jj;
            int h = idx >> 5, c32 = idx & 31;
            int gidx = h*64 + gid*32 + c32;
            uint2 vh = qh4[gidx], vl = ql4[gidx];
            uint32_t off = h*QPITCH + (gid*128 + c32*4)*2;
            *(uint2*)(smem + ASM_QH + off) = vh;
            *(uint2*)(smem + ASM_QL + off) = vl;
        }
    }
    if (tid < 128) sp[tid] = spat[(size_t)bk*128 + tid];
    for (int j = tid; j < 648; j += 256) tab[j] = table[j];

    #pragma unroll
    for (int rr = 0; rr < 16; rr++) {
        int c = gid*128 + rr*8 + cg;
        uint32_t h0, l0, h1, l1;
        split2t(f[rr].x, f[rr].y, h0, l0);
        split2t(f[rr].z, f[rr].w, h1, l1);
        uint32_t off = c*FPITCH + v*8;
        *(uint2*)(smem + ASM_FH + off) = make_uint2(h0, h1);
        *(uint2*)(smem + ASM_FL + off) = make_uint2(l0, l1);
    }
    asm volatile("bar.sync %0, 128;" :: "r"(1 + gid) : "memory");

    // phase 1: two independent accumulator chains
    {
        const int mt = w & 3, kh = gid;
        const int l15 = lane & 15;
        float dA[4] = {0.f,0.f,0.f,0.f}, dB[4] = {0.f,0.f,0.f,0.f};
        const uint32_t bBase = sb + ASM_QH +
            (uint32_t)((lane & 7)*QPITCH + ((lane >> 3) & 1)*16);
        #pragma unroll
        for (int kk = 0; kk < 8; kk += 2) {
            #pragma unroll
            for (int p = 0; p < 2; p++) {
                const int k16 = kh*8 + kk + p;
                uint32_t aaddr = sb + ASM_FH +
                    (uint32_t)((k16*16 + l15)*FPITCH + mt*32 + (lane >> 4)*16);
                uint32_t r0[4], r1[4];
                ldsm_x4_t(r0, aaddr);
                ldsm_x4_t(r1, aaddr + (ASM_FL - ASM_FH));
                uint32_t ah[4] = { r0[0], r0[2], r0[1], r0[3] };
                uint32_t al[4] = { r1[0], r1[2], r1[1], r1[3] };
                uint32_t bh[2], bl[2];
                ldsm_x2(bh, bBase + k16*32);
                ldsm_x2(bl, bBase + k16*32 + (ASM_QL - ASM_QH));
                if (p == 0) {
                    mma_bf16(dA, ah, bh[0], bh[1]);
                    mma_bf16(dA, ah, bl[0], bl[1]);
                    mma_bf16(dA, al, bh[0], bh[1]);
                } else {
                    mma_bf16(dB, ah, bh[0], bh[1]);
                    mma_bf16(dB, ah, bl[0], bl[1]);
                    mma_bf16(dB, al, bh[0], bh[1]);
                }
            }
        }
        const int g = lane >> 2, tg = lane & 3;
        float* dst = scp + kh*640;
        *(float2*)&dst[(mt*16 + g)*10 + tg*2]     = make_float2(dA[0]+dB[0], dA[1]+dB[1]);
        *(float2*)&dst[(mt*16 + g + 8)*10 + tg*2] = make_float2(dA[2]+dB[2], dA[3]+dB[3]);
    }
    __syncthreads();

    // combine + bias + softmax
    {
        int n0 = lane, n1 = lane + 32;
        float v0 = scp[n0*10 + w] + scp[640 + n0*10 + w] + grid_bias(sp, tab, w, n0);
        float v1 = scp[n1*10 + w] + scp[640 + n1*10 + w] + grid_bias(sp, tab, w, n1);
        float m = fmaxf(v0, v1);
        #pragma unroll
        for (int o = 16; o > 0; o >>= 1) m = fmaxf(m, __shfl_xor_sync(0xffffffffu, m, o));
        float e0 = expf(v0 - m), e1 = expf(v1 - m);
        float s = e0 + e1;
        #pragma unroll
        for (int o = 16; o > 0; o >>= 1) s += __shfl_xor_sync(0xffffffffu, s, o);
        float inv = 1.f/s;
        float p0 = e0*inv, p1 = e1*inv;
        __nv_bfloat16 h0 = __float2bfloat16_rn(p0);
        __nv_bfloat16 l0 = __float2bfloat16_rn(p0 - __bfloat162float(h0));
        __nv_bfloat16 h1 = __float2bfloat16_rn(p1);
        __nv_bfloat16 l1 = __float2bfloat16_rn(p1 - __bfloat162float(h1));
        *(__nv_bfloat16*)(smem + ASM_PH + w*PPITCH + lane*2)      = h0;
        *(__nv_bfloat16*)(smem + ASM_PL + w*PPITCH + lane*2)      = l0;
        *(__nv_bfloat16*)(smem + ASM_PH + w*PPITCH + (lane+32)*2) = h1;
        *(__nv_bfloat16*)(smem + ASM_PL + w*PPITCH + (lane+32)*2) = l1;
    }
    __syncthreads();

    // phase 2: four independent accumulator chains
    {
        const int l15 = lane & 15, l16 = lane >> 4;
        float d0a[4] = {0.f,0.f,0.f,0.f}, d0b[4] = {0.f,0.f,0.f,0.f};
        float d1a[4] = {0.f,0.f,0.f,0.f}, d1b[4] = {0.f,0.f,0.f,0.f};
        const uint32_t bBase = sb + ASM_PH +
            (uint32_t)((lane & 7)*PPITCH + ((lane >> 3) & 1)*16);
        #pragma unroll
        for (int k16 = 0; k16 < 4; k16++) {
            uint32_t bh[2], bl[2];
            ldsm_x2(bh, bBase + k16*32);
            ldsm_x2(bl, bBase + k16*32 + (ASM_PL - ASM_PH));
            uint32_t a0h[4], a0l[4], a1h[4], a1l[4];
            uint32_t aoff0 = sb + ASM_FH +
                (uint32_t)((w*16 + l15)*FPITCH + k16*32 + l16*16);
            uint32_t aoff1 = aoff0 + (uint32_t)(128*FPITCH);
            ldsm_x4(a0h, aoff0);
            ldsm_x4(a0l, aoff0 + (ASM_FL - ASM_FH));
            ldsm_x4(a1h, aoff1);
            ldsm_x4(a1l, aoff1 + (ASM_FL - ASM_FH));
            if (k16 & 1) {
                mma_bf16(d0b, a0h, bh[0], bh[1]);
                mma_bf16(d0b, a0h, bl[0], bl[1]);
                mma_bf16(d0b, a0l, bh[0], bh[1]);
                mma_bf16(d1b, a1h, bh[0], bh[1]);
                mma_bf16(d1b, a1h, bl[0], bl[1]);
                mma_bf16(d1b, a1l, bh[0], bh[1]);
            } else {
                mma_bf16(d0a, a0h, bh[0], bh[1]);
                mma_bf16(d0a, a0h, bl[0], bl[1]);
                mma_bf16(d0a, a0l, bh[0], bh[1]);
                mma_bf16(d1a, a1h, bh[0], bh[1]);
                mma_bf16(d1a, a1h, bl[0], bl[1]);
                mma_bf16(d1a, a1l, bh[0], bh[1]);
            }
        }
        const int g = lane >> 2, tg = lane & 3;
        *(float2*)&gt[(w*16 + g)*10 + tg*2]         = make_float2(d0a[0]+d0b[0], d0a[1]+d0b[1]);
        *(float2*)&gt[(w*16 + g + 8)*10 + tg*2]     = make_float2(d0a[2]+d0b[2], d0a[3]+d0b[3]);
        *(float2*)&gt[((w+8)*16 + g)*10 + tg*2]     = make_float2(d1a[0]+d1b[0], d1a[1]+d1b[1]);
        *(float2*)&gt[((w+8)*16 + g + 8)*10 + tg*2] = make_float2(d1a[2]+d1b[2], d1a[3]+d1b[3]);
    }
    __syncthreads();

    #pragma unroll
    for (int j = 0; j < 4; j++) {
        int idx = (tid + 256*j)*2;
        int h = idx >> 8, c = idx & 255;
        float v0 = gt[c*10 + h], v1 = gt[(c+1)*10 + h];
        uint32_t hh, ll;
        split2(v0, v1, hh, ll);
        size_t base = ((size_t)bk*HEADS + h)*C_ + c;
        *(uint32_t*)&gh[base] = hh;
        *(uint32_t*)&gl[base] = ll;
    }
}

// ---------------- LayerNorm over C=256 (one CTA per row) -------------------
template<bool HL>
__global__ void ln_kernel(const float* __restrict__ in, const float* __restrict__ gw,
                          const float* __restrict__ bw, float* __restrict__ out,
                          __nv_bfloat16* __restrict__ oh, __nv_bfloat16* __restrict__ ol)
{
    const int row = blockIdx.x, t = threadIdx.x;
    float v = in[(size_t)row*C_ + t];
    float s = v, ss = v*v;
    #pragma unroll
    for (int o = 16; o > 0; o >>= 1) {
        s  += __shfl_xor_sync(0xffffffffu, s,  o);
        ss += __shfl_xor_sync(0xffffffffu, ss, o);
    }
    __shared__ float rs[8], rss[8];
    int w = t >> 5, l = t & 31;
    if (l == 0) { rs[w] = s; rss[w] = ss; }
    __syncthreads();
    if (w == 0) {
        float a  = (l < 8) ? rs[l]  : 0.f;
        float b2 = (l < 8) ? rss[l] : 0.f;
        #pragma unroll
        for (int o = 4; o > 0; o >>= 1) {
            a  += __shfl_xor_sync(0xffffffffu, a,  o);
            b2 += __shfl_xor_sync(0xffffffffu, b2, o);
        }
        if (l == 0) { rs[0] = a; rss[0] = b2; }
    }
    __syncthreads();
    float mu  = rs[0]*(1.f/C_);
    float var = rss[0]*(1.f/C_) - mu*mu;
    float r = (v - mu)*rsqrtf(var + 1e-5f)*gw[t] + bw[t];
    size_t off = (size_t)row*C_ + t;
    out[off] = r;
    if (HL) {
        __nv_bfloat16 hb = __float2bfloat16_rn(r);
        oh[off] = hb;
        ol[off] = __float2bfloat16_rn(r - __bfloat162float(hb));
    }
}

// ---------------------------------------------------------------------------
extern "C" void kernel_launch(void* const* d_in, const int* in_sizes, int n_in,
                              void* d_out, int out_size)
{
    const float* query = (const float*)d_in[0];
    const float* lf    = (const float*)d_in[1];
    const float* spat  = (const float*)d_in[2];
    const float* table = (const float*)d_in[3];
    const float* Wq    = (const float*)d_in[4];
    const float* bq    = (const float*)d_in[5];
    const float* Wk    = (const float*)d_in[6];
    // d_in[7] = bk: constant over n -> cancels in softmax
    const float* Wv    = (const float*)d_in[8];
    const float* bv    = (const float*)d_in[9];
    const float* Wo    = (const float*)d_in[10];
    const float* bo    = (const float*)d_in[11];
    const float* ln1g  = (const float*)d_in[12];
    const float* ln1b  = (const float*)d_in[13];
    const float* W1    = (const float*)d_in[14];
    const float* b1    = (const float*)d_in[15];
    const float* W2    = (const float*)d_in[16];
    const float* b2    = (const float*)d_in[17];
    const float* ln2g  = (const float*)d_in[18];
    const float* ln2b  = (const float*)d_in[19];
    float* out = (float*)d_out;

    float *yb, *xb;
    cudaGetSymbolAddress((void**)&yb, d_y);
    cudaGetSymbolAddress((void**)&xb, d_x);

    __nv_bfloat16 *wqh,*wql,*wvh,*wvl,*woh,*wol,*w1h,*w1l,*w2h,*w2l,*wkth,*wktl;
    __nv_bfloat16 *qh,*ql,*qph,*qpl,*qkh,*qkl,*gh,*gl,*ch,*cl,*xh,*xl,*h1h,*h1l;
    cudaGetSymbolAddress((void**)&wqh, d_wqh); cudaGetSymbolAddress((void**)&wql, d_wql);
    cudaGetSymbolAddress((void**)&wvh, d_wvh); cudaGetSymbolAddress((void**)&wvl, d_wvl);
    cudaGetSymbolAddress((void**)&woh, d_woh); cudaGetSymbolAddress((void**)&wol, d_wol);
    cudaGetSymbolAddress((void**)&w1h, d_w1h); cudaGetSymbolAddress((void**)&w1l, d_w1l);
    cudaGetSymbolAddress((void**)&w2h, d_w2h); cudaGetSymbolAddress((void**)&w2l, d_w2l);
    cudaGetSymbolAddress((void**)&wkth, d_wkth); cudaGetSymbolAddress((void**)&wktl, d_wktl);
    cudaGetSymbolAddress((void**)&qh,  d_qh);  cudaGetSymbolAddress((void**)&ql,  d_ql);
    cudaGetSymbolAddress((void**)&qph, d_qph); cudaGetSymbolAddress((void**)&qpl, d_qpl);
    cudaGetSymbolAddress((void**)&qkh, d_qkh); cudaGetSymbolAddress((void**)&qkl, d_qkl);
    cudaGetSymbolAddress((void**)&gh,  d_gh);  cudaGetSymbolAddress((void**)&gl,  d_gl);
    cudaGetSymbolAddress((void**)&ch,  d_ch);  cudaGetSymbolAddress((void**)&cl,  d_cl);
    cudaGetSymbolAddress((void**)&xh,  d_xh);  cudaGetSymbolAddress((void**)&xl,  d_xl);
    cudaGetSymbolAddress((void**)&h1h, d_h1h); cudaGetSymbolAddress((void**)&h1l, d_h1l);

    cudaFuncSetAttribute(attn_kernel, cudaFuncAttributeMaxDynamicSharedMemorySize,
                         ATTN_SMEM_BYTES);

    const int SM64_2   = 2*(2*128*80 + 2*32*144);  // 59392 (M128 TN64, qk)
    const int SM64T32  = 3*(2*64*80 + 2*32*80);    // 46080 (M64 TN32 S3)
    const int SM64T64  = 3*(2*64*80 + 2*32*144);   // 58368 (M64 TN64 S3)
    cudaFuncSetAttribute((const void*)mma_gemm<64,2,false,false,false,false,true>,
                         cudaFuncAttributeMaxDynamicSharedMemorySize, SM64_2);
    cudaFuncSetAttribute((const void*)mma_gemm64<32,3,true,false,false,false,true>,
                         cudaFuncAttributeMaxDynamicSharedMemorySize, SM64T32);
    cudaFuncSetAttribute((const void*)mma_gemm64<32,3,true,true,false,true,false>,
                         cudaFuncAttributeMaxDynamicSharedMemorySize, SM64T32);
    cudaFuncSetAttribute((const void*)mma_gemm64<64,3,true,false,true,false,true>,
                         cudaFuncAttributeMaxDynamicSharedMemorySize, SM64T64);

    dim3 blk(256);

    // 1-3) conversion kernels
    conv_w<<<704, blk>>>(Wq, Wv, Wo, W1, W2,
                         wqh, wql, wvh, wvl, woh, wol, w1h, w1l, w2h, w2l);
    conv_q<<<1024, blk>>>(query, qh, ql);
    conv_wkt<<<16, blk>>>(Wk, wkth, wktl);
    // 4) qp = query @ Wq + bq  (hi/lo out, M64 TN32 -> 512 CTAs)  [profiled #4]
    mma_gemm64<32,3,true,false,false,false,true><<<dim3(C_/32, NT/64, 1), blk, SM64T32>>>(
        qh, ql, C_, wqh, wql, C_, bq, nullptr, nullptr, qph, qpl, C_, C_, 0,0,0,0);
    // 5) qk = qp_h @ (scale*Wk^T)_h  (K=32 single chunk, M128 TN64, 1024 CTAs)
    mma_gemm<64,2,false,false,false,false,true><<<dim3(C_/64, NT/128, HEADS), blk, SM64_2>>>(
        qph, qpl, C_, wkth, wktl, C_, nullptr, nullptr, nullptr, qkh, qkl,
        HEADS*C_, DH, /*za=*/DH, /*zw=*/DH*C_, /*zb=*/0, /*zo=*/C_);
    // 6) fused local attention v6 -> g (bf16 hi/lo)
    attn_kernel<<<NT, blk, ATTN_SMEM_BYTES>>>(lf, spat, table, qkh, qkl, gh, gl);
    // 7) ctx = g @ Wv_h + bv (8 head-batched, M64 TN32 -> 512 CTAs)
    mma_gemm64<32,3,true,false,false,false,true><<<dim3(1, NT/64, HEADS), blk, SM64T32>>>(
        gh, gl, HEADS*C_, wvh, wvl, C_, bv, nullptr, nullptr, ch, cl, C_, C_,
        /*za=*/C_, /*zw=*/DH, /*zb=*/DH, /*zo=*/DH);
    // 8) y = query + ctx @ Wo + bo (fp32 out, M64 TN32 -> 512 CTAs)
    mma_gemm64<32,3,true,true,false,true,false><<<dim3(C_/32, NT/64, 1), blk, SM64T32>>>(
        ch, cl, C_, woh, wol, C_, bo, query, yb, nullptr, nullptr, C_, C_, 0,0,0,0);
    // 9) x = LN1(y) (fp32 + hi/lo)
    ln_kernel<true><<<NT, blk>>>(yb, ln1g, ln1b, xb, xh, xl);
    // 10) h1 = gelu(x @ W1 + b1) (hi/lo out, M64 TN64 -> 1024 CTAs)
    mma_gemm64<64,3,true,false,true,false,true><<<dim3(FF_/64, NT/64, 1), blk, SM64T64>>>(
        xh, xl, C_, w1h, w1l, FF_, b1, nullptr, nullptr, h1h, h1l, FF_, C_, 0,0,0,0);
    // 11) y = x + h1 @ W2 + b2 (fp32 out, M64 TN32 -> 512 CTAs, K=1024)
    mma_gemm64<32,3,true,true,false,true,false><<<dim3(C_/32, NT/64, 1), blk, SM64T32>>>(
        h1h, h1l, FF_, w2h, w2l, C_, b2, xb, yb, nullptr, nullptr, C_, FF_, 0,0,0,0);
    // 12) out = LN2(y)
    ln_kernel<false><<<NT, blk>>>(yb, ln2g, ln2b, out, nullptr, nullptr);
}

// round 13
// speedup vs baseline: 1.0857x; 1.0857x over previous
#include <cuda_runtime.h>
#include <cuda_bf16.h>
#include <math.h>
#include <cstdint>

// Problem constants
#define B_    8
#define KTOK  512
#define C_    256
#define HEADS 8
#define DH    32
#define NS    64
#define FF_   1024
#define NT    (B_*KTOK)   // 4096 tokens

// ---------------- scratch (device globals; no allocation allowed) ----------
__device__ float d_y [NT*C_];
__device__ float d_x [NT*C_];

__device__ __nv_bfloat16 d_wqh[C_*C_],  d_wql[C_*C_];
__device__ __nv_bfloat16 d_wvh[C_*C_],  d_wvl[C_*C_];
__device__ __nv_bfloat16 d_woh[C_*C_],  d_wol[C_*C_];
__device__ __nv_bfloat16 d_w1h[C_*FF_], d_w1l[C_*FF_];
__device__ __nv_bfloat16 d_w2h[FF_*C_], d_w2l[FF_*C_];
__device__ __nv_bfloat16 d_wkth[C_*C_], d_wktl[C_*C_];   // scale * Wk^T
__device__ __nv_bfloat16 d_qh [NT*C_],  d_ql [NT*C_];    // query
__device__ __nv_bfloat16 d_qph[NT*C_],  d_qpl[NT*C_];    // q projection
__device__ __nv_bfloat16 d_qkh[NT*HEADS*C_], d_qkl[NT*HEADS*C_];
__device__ __nv_bfloat16 d_gh [NT*HEADS*C_], d_gl [NT*HEADS*C_];
__device__ __nv_bfloat16 d_ch [NT*C_],  d_cl [NT*C_];
__device__ __nv_bfloat16 d_xh [NT*C_],  d_xl [NT*C_];
__device__ __nv_bfloat16 d_h1h[NT*FF_], d_h1l[NT*FF_];

__device__ __forceinline__ float gelu_tanh(float x) {
    float x3 = x*x*x;
    return 0.5f*x*(1.f + tanhf(0.7978845608028654f*(x + 0.044715f*x3)));
}

__device__ __forceinline__ uint32_t smem_u32(const void* p) {
    uint32_t a;
    asm("{ .reg .u64 t; cvta.to.shared.u64 t, %1; cvt.u32.u64 %0, t; }" : "=r"(a) : "l"(p));
    return a;
}

// ---- ldmatrix / mma.sync / cp.async wrappers (arch-agnostic, sm_80+) -------
__device__ __forceinline__ void ldsm_x4(uint32_t (&r)[4], uint32_t addr) {
    asm volatile("ldmatrix.sync.aligned.m8n8.x4.shared.b16 {%0,%1,%2,%3}, [%4];"
        : "=r"(r[0]), "=r"(r[1]), "=r"(r[2]), "=r"(r[3]) : "r"(addr));
}
__device__ __forceinline__ void ldsm_x4_t(uint32_t (&r)[4], uint32_t addr) {
    asm volatile("ldmatrix.sync.aligned.m8n8.x4.trans.shared.b16 {%0,%1,%2,%3}, [%4];"
        : "=r"(r[0]), "=r"(r[1]), "=r"(r[2]), "=r"(r[3]) : "r"(addr));
}
__device__ __forceinline__ void ldsm_x2(uint32_t (&r)[2], uint32_t addr) {
    asm volatile("ldmatrix.sync.aligned.m8n8.x2.shared.b16 {%0,%1}, [%2];"
        : "=r"(r[0]), "=r"(r[1]) : "r"(addr));
}
__device__ __forceinline__ void ldsm_x4_t2(uint32_t (&r)[4], uint32_t addr) {
    asm volatile("ldmatrix.sync.aligned.m8n8.x4.trans.shared.b16 {%0,%1,%2,%3}, [%4];"
        : "=r"(r[0]), "=r"(r[1]), "=r"(r[2]), "=r"(r[3]) : "r"(addr));
}
__device__ __forceinline__ void mma_bf16(float (&d)[4], const uint32_t (&a)[4],
                                         uint32_t b0, uint32_t b1) {
    asm volatile(
        "mma.sync.aligned.m16n8k16.row.col.f32.bf16.bf16.f32 "
        "{%0,%1,%2,%3}, {%4,%5,%6,%7}, {%8,%9}, {%0,%1,%2,%3};"
        : "+f"(d[0]), "+f"(d[1]), "+f"(d[2]), "+f"(d[3])
        : "r"(a[0]), "r"(a[1]), "r"(a[2]), "r"(a[3]), "r"(b0), "r"(b1));
}
__device__ __forceinline__ void cp16(uint32_t dst, const void* src) {
    asm volatile("cp.async.cg.shared.global [%0], [%1], 16;" :: "r"(dst), "l"(src));
}
#define CP_COMMIT() asm volatile("cp.async.commit_group;" ::: "memory")
#define CP_WAIT(n)  asm volatile("cp.async.wait_group %0;" :: "n"(n) : "memory")

// round-to-nearest hi/lo split (weights, outputs)
__device__ __forceinline__ void split2(float x, float y, uint32_t& h, uint32_t& l) {
    __nv_bfloat162 hh = __floats2bfloat162_rn(x, y);
    float rx = x - __bfloat162float(hh.x);
    float ry = y - __bfloat162float(hh.y);
    __nv_bfloat162 ll = __floats2bfloat162_rn(rx, ry);
    h = *(uint32_t*)&hh;  l = *(uint32_t*)&ll;
}
// truncation hi/lo split (cheaper; residual <= 2^-17 rel) — attn feats hot path
__device__ __forceinline__ void split2t(float x, float y, uint32_t& h, uint32_t& l) {
    uint32_t bx = __float_as_uint(x), by = __float_as_uint(y);
    h = (bx >> 16) | (by & 0xFFFF0000u);
    float lx = x - __uint_as_float(bx & 0xFFFF0000u);
    float ly = y - __uint_as_float(by & 0xFFFF0000u);
    __nv_bfloat162 ll = __floats2bfloat162_rn(lx, ly);
    l = *(uint32_t*)&ll;
}

// ---------------- single merged conversion kernel ----------------------------
__device__ __forceinline__ void seg_split(const float* __restrict__ in,
                                          __nv_bfloat16* __restrict__ oh,
                                          __nv_bfloat16* __restrict__ ol,
                                          int blk, int tid)
{
    int i = blk*256 + tid;
    float4 v = ((const float4*)in)[i];
    uint32_t h0, l0, h1, l1;
    split2(v.x, v.y, h0, l0);
    split2(v.z, v.w, h1, l1);
    ((uint2*)oh)[i] = make_uint2(h0, h1);
    ((uint2*)ol)[i] = make_uint2(l0, l1);
}

__global__ void conv_all(const float* __restrict__ query, const float* __restrict__ Wq,
                         const float* __restrict__ Wv, const float* __restrict__ Wo,
                         const float* __restrict__ W1, const float* __restrict__ W2,
                         const float* __restrict__ Wk,
                         __nv_bfloat16* qh, __nv_bfloat16* ql,
                         __nv_bfloat16* wqh, __nv_bfloat16* wql,
                         __nv_bfloat16* wvh, __nv_bfloat16* wvl,
                         __nv_bfloat16* woh, __nv_bfloat16* wol,
                         __nv_bfloat16* w1h, __nv_bfloat16* w1l,
                         __nv_bfloat16* w2h, __nv_bfloat16* w2l,
                         __nv_bfloat16* wkth, __nv_bfloat16* wktl)
{
    __shared__ float ts[64][65];
    const int bid = blockIdx.x, tid = threadIdx.x;
    if      (bid < 1024) seg_split(query, qh, ql, bid, tid);
    else if (bid < 1088) seg_split(Wq, wqh, wql, bid - 1024, tid);
    else if (bid < 1152) seg_split(Wv, wvh, wvl, bid - 1088, tid);
    else if (bid < 1216) seg_split(Wo, woh, wol, bid - 1152, tid);
    else if (bid < 1472) seg_split(W1, w1h, w1l, bid - 1216, tid);
    else if (bid < 1728) seg_split(W2, w2h, w2l, bid - 1472, tid);
    else {
        const int t = bid - 1728;
        const int tc = (t >> 2)*64, td = (t & 3)*64;
        #pragma unroll
        for (int j = 0; j < 4; j++) {
            int idx = tid + 256*j;
            int r = idx >> 4, q = idx & 15;
            float4 v = *(const float4*)&Wk[(size_t)(tc + r)*C_ + td + q*4];
            ts[r][q*4+0] = v.x; ts[r][q*4+1] = v.y;
            ts[r][q*4+2] = v.z; ts[r][q*4+3] = v.w;
        }
        __syncthreads();
        const float scale = 0.17677669529663687f;   // 1/sqrt(32)
        #pragma unroll
        for (int j = 0; j < 4; j++) {
            int idx = tid + 256*j;
            int r2 = idx >> 4, q2 = idx & 15;
            float v0 = ts[q2*4+0][r2]*scale, v1 = ts[q2*4+1][r2]*scale;
            float v2 = ts[q2*4+2][r2]*scale, v3 = ts[q2*4+3][r2]*scale;
            uint32_t h0, l0, h1, l1;
            split2(v0, v1, h0, l0);
            split2(v2, v3, h1, l1);
            size_t e = (size_t)(td + r2)*C_ + tc + q2*4;
            *(uint2*)&wkth[e] = make_uint2(h0, h1);
            *(uint2*)&wktl[e] = make_uint2(l0, l1);
        }
    }
}

// ======= bf16 hi/lo tensor-core GEMM, cp.async pipelined (round-11 best) ====
template<int TN, int S, bool BIAS, bool RES, bool GELU, bool OF32, bool OHL>
__global__ __launch_bounds__(256, 2)
void mma_gemm(const __nv_bfloat16* __restrict__ Ah, const __nv_bfloat16* __restrict__ Al,
              int lda,
              const __nv_bfloat16* __restrict__ Bh, const __nv_bfloat16* __restrict__ Bl,
              int ldw,
              const float* __restrict__ bias, const float* __restrict__ res,
              float* __restrict__ Out, __nv_bfloat16* __restrict__ OutH,
              __nv_bfloat16* __restrict__ OutL,
              int ldo, int K, int za, int zw, int zb, int zo)
{
    constexpr int AROW   = 80;
    constexpr int BROW   = TN*2 + 16;
    constexpr int A_BYTES = 128*AROW;
    constexpr int B_BYTES = 32*BROW;
    constexpr int STAGE  = 2*A_BYTES + 2*B_BYTES;
    constexpr int NB16   = TN/32;
    constexpr int BCH    = TN/8;
    constexpr int BCHT   = 32*BCH;

    extern __shared__ char smem[];
    const uint32_t sb = smem_u32(smem);
    const int tid  = threadIdx.x;
    const int lane = tid & 31, wid = tid >> 5;
    const int wm = wid & 3, wn = wid >> 2;
    const int m0 = blockIdx.y*128, n0 = blockIdx.x*TN;
    const int z = blockIdx.z;
    Ah += (size_t)z*za;  Al += (size_t)z*za;
    Bh += (size_t)z*zw;  Bl += (size_t)z*zw;
    if (OF32) Out += (size_t)z*zo;
    if (OHL) { OutH += (size_t)z*zo; OutL += (size_t)z*zo; }
    if (BIAS) bias += (size_t)z*zb;
    if (RES)  res  += (size_t)z*zo;

    float acc[2][NB16*2][4];
    #pragma unroll
    for (int a = 0; a < 2; a++)
        #pragma unroll
        for (int b = 0; b < NB16*2; b++)
            #pragma unroll
            for (int c = 0; c < 4; c++) acc[a][b][c] = 0.f;

    auto issue = [&](int chunk, int s) {
        const uint32_t sa = sb + s*STAGE;
        const int kc = chunk*32;
        #pragma unroll
        for (int j = 0; j < 2; j++) {
            int idx = tid + 256*j;
            int row = idx >> 2, ch = idx & 3;
            size_t soff = (size_t)(m0 + row)*lda + kc + ch*8;
            uint32_t d = sa + row*AROW + ch*16;
            cp16(d,           Ah + soff);
            cp16(d + A_BYTES, Al + soff);
        }
        if (BCHT >= 256) {
            #pragma unroll
            for (int j = 0; j < BCHT/256; j++) {
                int idx = tid + 256*j;
                int row = idx / BCH, ch = idx % BCH;
                size_t soff = (size_t)(kc + row)*ldw + n0 + ch*8;
                uint32_t d = sa + 2*A_BYTES + row*BROW + ch*16;
                cp16(d,           Bh + soff);
                cp16(d + B_BYTES, Bl + soff);
            }
        } else {
            if (tid < BCHT) {
                int row = tid / BCH, ch = tid % BCH;
                size_t soff = (size_t)(kc + row)*ldw + n0 + ch*8;
                uint32_t d = sa + 2*A_BYTES + row*BROW + ch*16;
                cp16(d,           Bh + soff);
                cp16(d + B_BYTES, Bl + soff);
            }
        }
    };
    auto compute = [&](int s) {
        const uint32_t a_h = sb + s*STAGE;
        const uint32_t a_l = a_h + A_BYTES;
        const uint32_t b_h = a_h + 2*A_BYTES;
        const uint32_t b_l = b_h + B_BYTES;
        const int l15 = lane & 15, l16 = lane >> 4;
        #pragma unroll
        for (int k16 = 0; k16 < 2; k16++) {
            uint32_t ah[2][4], al[2][4];
            #pragma unroll
            for (int mt = 0; mt < 2; mt++) {
                uint32_t aoff = (uint32_t)((wm*32 + mt*16 + l15)*AROW + k16*32 + l16*16);
                ldsm_x4(ah[mt], a_h + aoff);
                ldsm_x4(al[mt], a_l + aoff);
            }
            #pragma unroll
            for (int nb = 0; nb < NB16; nb++) {
                uint32_t boff = (uint32_t)((k16*16 + l15)*BROW + (wn*(TN/2) + nb*16)*2 + l16*16);
                uint32_t bh[4], bl[4];
                ldsm_x4_t(bh, b_h + boff);
                ldsm_x4_t(bl, b_l + boff);
                #pragma unroll
                for (int mt = 0; mt < 2; mt++) {
                    mma_bf16(acc[mt][nb*2],   ah[mt], bh[0], bh[1]);
                    mma_bf16(acc[mt][nb*2],   ah[mt], bl[0], bl[1]);
                    mma_bf16(acc[mt][nb*2],   al[mt], bh[0], bh[1]);
                    mma_bf16(acc[mt][nb*2+1], ah[mt], bh[2], bh[3]);
                    mma_bf16(acc[mt][nb*2+1], ah[mt], bl[2], bl[3]);
                    mma_bf16(acc[mt][nb*2+1], al[mt], bh[2], bh[3]);
                }
            }
        }
    };

    const int NC = K/32;
    #pragma unroll
    for (int s = 0; s < S - 1; s++) {
        if (s < NC) issue(s, s);
        CP_COMMIT();
    }
    for (int i = 0; i < NC; i++) {
        CP_WAIT(S - 2);
        __syncthreads();
        const int nx = i + S - 1;
        if (nx < NC) issue(nx, nx % S);
        CP_COMMIT();
        compute(i % S);
    }

    const int g = lane >> 2, tg = lane & 3;
    #pragma unroll
    for (int mt = 0; mt < 2; mt++) {
        const int r0 = m0 + wm*32 + mt*16 + g;
        #pragma unroll
        for (int j = 0; j < NB16*2; j++) {
            const int col = n0 + wn*(TN/2) + j*8 + tg*2;
            float v0 = acc[mt][j][0], v1 = acc[mt][j][1];
            float v2 = acc[mt][j][2], v3 = acc[mt][j][3];
            if (BIAS) {
                float b0 = bias[col], b1 = bias[col+1];
                v0 += b0; v1 += b1; v2 += b0; v3 += b1;
            }
            if (RES) {
                const float* rp0 = &res[(size_t)r0*ldo + col];
                const float* rp1 = &res[(size_t)(r0+8)*ldo + col];
                v0 += rp0[0]; v1 += rp0[1]; v2 += rp1[0]; v3 += rp1[1];
            }
            if (GELU) { v0 = gelu_tanh(v0); v1 = gelu_tanh(v1);
                        v2 = gelu_tanh(v2); v3 = gelu_tanh(v3); }
            if (OF32) {
                *(float2*)&Out[(size_t)r0*ldo + col]     = make_float2(v0, v1);
                *(float2*)&Out[(size_t)(r0+8)*ldo + col] = make_float2(v2, v3);
            }
            if (OHL) {
                uint32_t h0, l0, h1, l1;
                split2(v0, v1, h0, l0);
                split2(v2, v3, h1, l1);
                *(uint32_t*)&OutH[(size_t)r0*ldo + col]     = h0;
                *(uint32_t*)&OutL[(size_t)r0*ldo + col]     = l0;
                *(uint32_t*)&OutH[(size_t)(r0+8)*ldo + col] = h1;
                *(uint32_t*)&OutL[(size_t)(r0+8)*ldo + col] = l1;
            }
        }
    }
}

// ---- bilinear tap of the 9x9 rel-pos table ---------------------------------
__device__ __forceinline__ float bil_corner(const float* __restrict__ th,
                                            int yi, int xi, float w)
{
    if (xi < 0 || xi > 8 || yi < 0 || yi > 8) return 0.f;
    return th[yi*9 + xi]*w;
}
__device__ __forceinline__ float grid_bias(const float* __restrict__ sp,
                                           const float* __restrict__ tab,
                                           int h, int n)
{
    float gx = (sp[2*n]   + 1.f)*4.f;
    float gy = (sp[2*n+1] + 1.f)*4.f;
    float x0f = floorf(gx), y0f = floorf(gy);
    int   x0 = (int)x0f,    y0 = (int)y0f;
    float wx1 = gx - x0f, wx0 = 1.f - wx1;
    float wy1 = gy - y0f, wy0 = 1.f - wy1;
    const float* th = &tab[h*81];
    return bil_corner(th, y0,   x0,   wy0*wx0)
         + bil_corner(th, y0,   x0+1, wy0*wx1)
         + bil_corner(th, y0+1, x0,   wy1*wx0)
         + bil_corner(th, y0+1, x0+1, wy1*wx1);
}

// ---------------- fused local attention v7 (direct g stores) ----------------
#define ASM_FH   0
#define ASM_FL   36864
#define ASM_PH   73728
#define ASM_PL   74880
#define ASM_SP   76032
#define ASM_TAB  76544
#define ASM_QH   79168
#define ASM_QL   83392
#define ASM_SCP  87616
#define ATTN_SMEM_BYTES 92736
#define FPITCH 144
#define QPITCH 528
#define PPITCH 144

__global__ __launch_bounds__(256, 2)
void attn_kernel(const float* __restrict__ lf,   const float* __restrict__ spat,
                 const float* __restrict__ table,
                 const __nv_bfloat16* __restrict__ qkh,
                 const __nv_bfloat16* __restrict__ qkl,
                 __nv_bfloat16* __restrict__ gh, __nv_bfloat16* __restrict__ gl)
{
    extern __shared__ char smem[];
    float* scp = (float*)(smem + ASM_SCP);
    float* sp  = (float*)(smem + ASM_SP);
    float* tab = (float*)(smem + ASM_TAB);
    const uint32_t sb = smem_u32(smem);

    const int tid  = threadIdx.x;
    const int lane = tid & 31, w = tid >> 5;
    const int gid  = tid >> 7, lt = tid & 127;
    const int bk = blockIdx.x;
    const int b  = bk >> 9, k = bk & 511;

    const float* lfb = lf + (size_t)b*(C_*KTOK*NS) + (size_t)k*NS;
    const int v = lt & 15, cg = lt >> 4;
    float4 f[16];
    #pragma unroll
    for (int rr = 0; rr < 16; rr++) {
        int c = gid*128 + rr*8 + cg;
        f[rr] = *(const float4*)(lfb + (size_t)c*(KTOK*NS) + v*4);
    }
    {
        const uint2* qh4 = (const uint2*)(qkh + (size_t)bk*2048);
        const uint2* ql4 = (const uint2*)(qkl + (size_t)bk*2048);
        #pragma unroll
        for (int jj = 0; jj < 2; jj++) {
            int idx = lt + 128*jj;
            int h = idx >> 5, c32 = idx & 31;
            int gidx = h*64 + gid*32 + c32;
            uint2 vh = qh4[gidx], vl = ql4[gidx];
            uint32_t off = h*QPITCH + (gid*128 + c32*4)*2;
            *(uint2*)(smem + ASM_QH + off) = vh;
            *(uint2*)(smem + ASM_QL + off) = vl;
        }
    }
    if (tid < 128) sp[tid] = spat[(size_t)bk*128 + tid];
    for (int j = tid; j < 648; j += 256) tab[j] = table[j];

    #pragma unroll
    for (int rr = 0; rr < 16; rr++) {
        int c = gid*128 + rr*8 + cg;
        uint32_t h0, l0, h1, l1;
        split2t(f[rr].x, f[rr].y, h0, l0);
        split2t(f[rr].z, f[rr].w, h1, l1);
        uint32_t off = c*FPITCH + v*8;
        *(uint2*)(smem + ASM_FH + off) = make_uint2(h0, h1);
        *(uint2*)(smem + ASM_FL + off) = make_uint2(l0, l1);
    }
    asm volatile("bar.sync %0, 128;" :: "r"(1 + gid) : "memory");

    // phase 1: two independent accumulator chains
    {
        const int mt = w & 3, kh = gid;
        const int l15 = lane & 15;
        float dA[4] = {0.f,0.f,0.f,0.f}, dB[4] = {0.f,0.f,0.f,0.f};
        const uint32_t bBase = sb + ASM_QH +
            (uint32_t)((lane & 7)*QPITCH + ((lane >> 3) & 1)*16);
        #pragma unroll
        for (int kk = 0; kk < 8; kk += 2) {
            #pragma unroll
            for (int p = 0; p < 2; p++) {
                const int k16 = kh*8 + kk + p;
                uint32_t aaddr = sb + ASM_FH +
                    (uint32_t)((k16*16 + l15)*FPITCH + mt*32 + (lane >> 4)*16);
                uint32_t r0[4], r1[4];
                ldsm_x4_t(r0, aaddr);
                ldsm_x4_t(r1, aaddr + (ASM_FL - ASM_FH));
                uint32_t ah[4] = { r0[0], r0[2], r0[1], r0[3] };
                uint32_t al[4] = { r1[0], r1[2], r1[1], r1[3] };
                uint32_t bh[2], bl[2];
                ldsm_x2(bh, bBase + k16*32);
                ldsm_x2(bl, bBase + k16*32 + (ASM_QL - ASM_QH));
                if (p == 0) {
                    mma_bf16(dA, ah, bh[0], bh[1]);
                    mma_bf16(dA, ah, bl[0], bl[1]);
                    mma_bf16(dA, al, bh[0], bh[1]);
                } else {
                    mma_bf16(dB, ah, bh[0], bh[1]);
                    mma_bf16(dB, ah, bl[0], bl[1]);
                    mma_bf16(dB, al, bh[0], bh[1]);
                }
            }
        }
        const int g = lane >> 2, tg = lane & 3;
        float* dst = scp + kh*640;
        *(float2*)&dst[(mt*16 + g)*10 + tg*2]     = make_float2(dA[0]+dB[0], dA[1]+dB[1]);
        *(float2*)&dst[(mt*16 + g + 8)*10 + tg*2] = make_float2(dA[2]+dB[2], dA[3]+dB[3]);
    }
    __syncthreads();

    // combine + bias + softmax
    {
        int n0 = lane, n1 = lane + 32;
        float v0 = scp[n0*10 + w] + scp[640 + n0*10 + w] + grid_bias(sp, tab, w, n0);
        float v1 = scp[n1*10 + w] + scp[640 + n1*10 + w] + grid_bias(sp, tab, w, n1);
        float m = fmaxf(v0, v1);
        #pragma unroll
        for (int o = 16; o > 0; o >>= 1) m = fmaxf(m, __shfl_xor_sync(0xffffffffu, m, o));
        float e0 = expf(v0 - m), e1 = expf(v1 - m);
        float s = e0 + e1;
        #pragma unroll
        for (int o = 16; o > 0; o >>= 1) s += __shfl_xor_sync(0xffffffffu, s, o);
        float inv = 1.f/s;
        float p0 = e0*inv, p1 = e1*inv;
        __nv_bfloat16 h0 = __float2bfloat16_rn(p0);
        __nv_bfloat16 l0 = __float2bfloat16_rn(p0 - __bfloat162float(h0));
        __nv_bfloat16 h1 = __float2bfloat16_rn(p1);
        __nv_bfloat16 l1 = __float2bfloat16_rn(p1 - __bfloat162float(h1));
        *(__nv_bfloat16*)(smem + ASM_PH + w*PPITCH + lane*2)      = h0;
        *(__nv_bfloat16*)(smem + ASM_PL + w*PPITCH + lane*2)      = l0;
        *(__nv_bfloat16*)(smem + ASM_PH + w*PPITCH + (lane+32)*2) = h1;
        *(__nv_bfloat16*)(smem + ASM_PL + w*PPITCH + (lane+32)*2) = l1;
    }
    __syncthreads();

    // phase 2: four independent accumulator chains, DIRECT hi/lo stores
    {
        const int l15 = lane & 15, l16 = lane >> 4;
        float d0a[4] = {0.f,0.f,0.f,0.f}, d0b[4] = {0.f,0.f,0.f,0.f};
        float d1a[4] = {0.f,0.f,0.f,0.f}, d1b[4] = {0.f,0.f,0.f,0.f};
        const uint32_t bBase = sb + ASM_PH +
            (uint32_t)((lane & 7)*PPITCH + ((lane >> 3) & 1)*16);
        #pragma unroll
        for (int k16 = 0; k16 < 4; k16++) {
            uint32_t bh[2], bl[2];
            ldsm_x2(bh, bBase + k16*32);
            ldsm_x2(bl, bBase + k16*32 + (ASM_PL - ASM_PH));
            uint32_t a0h[4], a0l[4], a1h[4], a1l[4];
            uint32_t aoff0 = sb + ASM_FH +
                (uint32_t)((w*16 + l15)*FPITCH + k16*32 + l16*16);
            uint32_t aoff1 = aoff0 + (uint32_t)(128*FPITCH);
            ldsm_x4(a0h, aoff0);
            ldsm_x4(a0l, aoff0 + (ASM_FL - ASM_FH));
            ldsm_x4(a1h, aoff1);
            ldsm_x4(a1l, aoff1 + (ASM_FL - ASM_FH));
            if (k16 & 1) {
                mma_bf16(d0b, a0h, bh[0], bh[1]);
                mma_bf16(d0b, a0h, bl[0], bl[1]);
                mma_bf16(d0b, a0l, bh[0], bh[1]);
                mma_bf16(d1b, a1h, bh[0], bh[1]);
                mma_bf16(d1b, a1h, bl[0], bl[1]);
                mma_bf16(d1b, a1l, bh[0], bh[1]);
            } else {
                mma_bf16(d0a, a0h, bh[0], bh[1]);
                mma_bf16(d0a, a0h, bl[0], bl[1]);
                mma_bf16(d0a, a0l, bh[0], bh[1]);
                mma_bf16(d1a, a1h, bh[0], bh[1]);
                mma_bf16(d1a, a1h, bl[0], bl[1]);
                mma_bf16(d1a, a1l, bh[0], bh[1]);
            }
        }
        const int g = lane >> 2, tg = lane & 3;
        const size_t tokb = (size_t)bk*HEADS*C_;
        auto stg = [&](int c, int h, float val) {
            __nv_bfloat16 hb = __float2bfloat16_rn(val);
            __nv_bfloat16 lb = __float2bfloat16_rn(val - __bfloat162float(hb));
            gh[tokb + (size_t)h*C_ + c] = hb;
            gl[tokb + (size_t)h*C_ + c] = lb;
        };
        int c0 = w*16 + g, c1 = (w+8)*16 + g;
        int h0 = 2*tg, h1 = 2*tg + 1;
        stg(c0,     h0, d0a[0]+d0b[0]);  stg(c0,     h1, d0a[1]+d0b[1]);
        stg(c0 + 8, h0, d0a[2]+d0b[2]);  stg(c0 + 8, h1, d0a[3]+d0b[3]);
        stg(c1,     h0, d1a[0]+d1b[0]);  stg(c1,     h1, d1a[1]+d1b[1]);
        stg(c1 + 8, h0, d1a[2]+d1b[2]);  stg(c1 + 8, h1, d1a[3]+d1b[3]);
    }
}

// ---------------- LayerNorm over C=256, 4 rows/CTA, float4/thread -----------
template<bool HL>
__global__ void ln_kernel(const float* __restrict__ in, const float* __restrict__ gw,
                          const float* __restrict__ bw, float* __restrict__ out,
                          __nv_bfloat16* __restrict__ oh, __nv_bfloat16* __restrict__ ol)
{
    const int tid = threadIdx.x;
    const int rg = tid >> 6;           // 0..3 (row within group)
    const int lt = tid & 63;           // 0..63 (float4 index)
    const int row = blockIdx.x*4 + rg;
    const int wid = tid >> 5, lane = tid & 31;

    float4 v = ((const float4*)(in + (size_t)row*C_))[lt];
    float s  = v.x + v.y + v.z + v.w;
    float ss = v.x*v.x + v.y*v.y + v.z*v.z + v.w*v.w;
    #pragma unroll
    for (int o = 16; o > 0; o >>= 1) {
        s  += __shfl_xor_sync(0xffffffffu, s,  o);
        ss += __shfl_xor_sync(0xffffffffu, ss, o);
    }
    __shared__ float rs[8], rss[8];
    if (lane == 0) { rs[wid] = s; rss[wid] = ss; }
    __syncthreads();
    float S  = rs[rg*2]  + rs[rg*2 + 1];
    float SS = rss[rg*2] + rss[rg*2 + 1];
    float mu  = S*(1.f/C_);
    float var = SS*(1.f/C_) - mu*mu;
    float inv = rsqrtf(var + 1e-5f);

    float4 g4 = ((const float4*)gw)[lt];
    float4 b4 = ((const float4*)bw)[lt];
    float r0 = (v.x - mu)*inv*g4.x + b4.x;
    float r1 = (v.y - mu)*inv*g4.y + b4.y;
    float r2 = (v.z - mu)*inv*g4.z + b4.z;
    float r3 = (v.w - mu)*inv*g4.w + b4.w;
    ((float4*)(out + (size_t)row*C_))[lt] = make_float4(r0, r1, r2, r3);
    if (HL) {
        uint32_t h0, l0, h1, l1;
        split2(r0, r1, h0, l0);
        split2(r2, r3, h1, l1);
        ((uint2*)(oh + (size_t)row*C_))[lt] = make_uint2(h0, h1);
        ((uint2*)(ol + (size_t)row*C_))[lt] = make_uint2(l0, l1);
    }
}

// ---------------------------------------------------------------------------
extern "C" void kernel_launch(void* const* d_in, const int* in_sizes, int n_in,
                              void* d_out, int out_size)
{
    const float* query = (const float*)d_in[0];
    const float* lf    = (const float*)d_in[1];
    const float* spat  = (const float*)d_in[2];
    const float* table = (const float*)d_in[3];
    const float* Wq    = (const float*)d_in[4];
    const float* bq    = (const float*)d_in[5];
    const float* Wk    = (const float*)d_in[6];
    // d_in[7] = bk: constant over n -> cancels in softmax
    const float* Wv    = (const float*)d_in[8];
    const float* bv    = (const float*)d_in[9];
    const float* Wo    = (const float*)d_in[10];
    const float* bo    = (const float*)d_in[11];
    const float* ln1g  = (const float*)d_in[12];
    const float* ln1b  = (const float*)d_in[13];
    const float* W1    = (const float*)d_in[14];
    const float* b1    = (const float*)d_in[15];
    const float* W2    = (const float*)d_in[16];
    const float* b2    = (const float*)d_in[17];
    const float* ln2g  = (const float*)d_in[18];
    const float* ln2b  = (const float*)d_in[19];
    float* out = (float*)d_out;

    float *yb, *xb;
    cudaGetSymbolAddress((void**)&yb, d_y);
    cudaGetSymbolAddress((void**)&xb, d_x);

    __nv_bfloat16 *wqh,*wql,*wvh,*wvl,*woh,*wol,*w1h,*w1l,*w2h,*w2l,*wkth,*wktl;
    __nv_bfloat16 *qh,*ql,*qph,*qpl,*qkh,*qkl,*gh,*gl,*ch,*cl,*xh,*xl,*h1h,*h1l;
    cudaGetSymbolAddress((void**)&wqh, d_wqh); cudaGetSymbolAddress((void**)&wql, d_wql);
    cudaGetSymbolAddress((void**)&wvh, d_wvh); cudaGetSymbolAddress((void**)&wvl, d_wvl);
    cudaGetSymbolAddress((void**)&woh, d_woh); cudaGetSymbolAddress((void**)&wol, d_wol);
    cudaGetSymbolAddress((void**)&w1h, d_w1h); cudaGetSymbolAddress((void**)&w1l, d_w1l);
    cudaGetSymbolAddress((void**)&w2h, d_w2h); cudaGetSymbolAddress((void**)&w2l, d_w2l);
    cudaGetSymbolAddress((void**)&wkth, d_wkth); cudaGetSymbolAddress((void**)&wktl, d_wktl);
    cudaGetSymbolAddress((void**)&qh,  d_qh);  cudaGetSymbolAddress((void**)&ql,  d_ql);
    cudaGetSymbolAddress((void**)&qph, d_qph); cudaGetSymbolAddress((void**)&qpl, d_qpl);
    cudaGetSymbolAddress((void**)&qkh, d_qkh); cudaGetSymbolAddress((void**)&qkl, d_qkl);
    cudaGetSymbolAddress((void**)&gh,  d_gh);  cudaGetSymbolAddress((void**)&gl,  d_gl);
    cudaGetSymbolAddress((void**)&ch,  d_ch);  cudaGetSymbolAddress((void**)&cl,  d_cl);
    cudaGetSymbolAddress((void**)&xh,  d_xh);  cudaGetSymbolAddress((void**)&xl,  d_xl);
    cudaGetSymbolAddress((void**)&h1h, d_h1h); cudaGetSymbolAddress((void**)&h1l, d_h1l);

    cudaFuncSetAttribute(attn_kernel, cudaFuncAttributeMaxDynamicSharedMemorySize,
                         ATTN_SMEM_BYTES);

    const int SM64_2 = 2*(2*128*80 + 2*32*144);   // 59392
    const int SM64_3 = 3*(2*128*80 + 2*32*144);   // 89088
    const int SM32_3 = 3*(2*128*80 + 2*32*80);    // 76800
    cudaFuncSetAttribute((const void*)mma_gemm<32,3,true,false,false,false,true>,
                         cudaFuncAttributeMaxDynamicSharedMemorySize, SM32_3);
    cudaFuncSetAttribute((const void*)mma_gemm<64,2,false,false,false,false,true>,
                         cudaFuncAttributeMaxDynamicSharedMemorySize, SM64_2);
    cudaFuncSetAttribute((const void*)mma_gemm<32,3,true,true,false,true,false>,
                         cudaFuncAttributeMaxDynamicSharedMemorySize, SM32_3);
    cudaFuncSetAttribute((const void*)mma_gemm<64,3,true,false,true,false,true>,
                         cudaFuncAttributeMaxDynamicSharedMemorySize, SM64_3);

    dim3 blk(256);

    // 1) merged conversion kernel (weights + query + scale*Wk^T)
    conv_all<<<1744, blk>>>(query, Wq, Wv, Wo, W1, W2, Wk,
                            qh, ql, wqh, wql, wvh, wvl, woh, wol,
                            w1h, w1l, w2h, w2l, wkth, wktl);
    // 2) qp = query @ Wq + bq  (hi/lo out, S=3)
    mma_gemm<32,3,true,false,false,false,true><<<dim3(C_/32, NT/128, 1), blk, SM32_3>>>(
        qh, ql, C_, wqh, wql, C_, bq, nullptr, nullptr, qph, qpl, C_, C_, 0,0,0,0);
    // 3) qk = qp_h @ (scale*Wk^T)_h  (K=32 single chunk, S=2)
    mma_gemm<64,2,false,false,false,false,true><<<dim3(C_/64, NT/128, HEADS), blk, SM64_2>>>(
        qph, qpl, C_, wkth, wktl, C_, nullptr, nullptr, nullptr, qkh, qkl,
        HEADS*C_, DH, /*za=*/DH, /*zw=*/DH*C_, /*zb=*/0, /*zo=*/C_);
    // 4) fused local attention v7 -> g (bf16 hi/lo, direct stores)
    attn_kernel<<<NT, blk, ATTN_SMEM_BYTES>>>(lf, spat, table, qkh, qkl, gh, gl);
    // 5) ctx = g @ Wv_h + bv (8 head-batched, hi/lo out, S=3)
    mma_gemm<32,3,true,false,false,false,true><<<dim3(1, NT/128, HEADS), blk, SM32_3>>>(
        gh, gl, HEADS*C_, wvh, wvl, C_, bv, nullptr, nullptr, ch, cl, C_, C_,
        /*za=*/C_, /*zw=*/DH, /*zb=*/DH, /*zo=*/DH);
    // 6) y = query + ctx @ Wo + bo (fp32 out, S=3)
    mma_gemm<32,3,true,true,false,true,false><<<dim3(C_/32, NT/128, 1), blk, SM32_3>>>(
        ch, cl, C_, woh, wol, C_, bo, query, yb, nullptr, nullptr, C_, C_, 0,0,0,0);
    // 7) x = LN1(y) (fp32 + hi/lo), 4 rows/CTA
    ln_kernel<true><<<NT/4, blk>>>(yb, ln1g, ln1b, xb, xh, xl);
    // 8) h1 = gelu(x @ W1 + b1) (hi/lo out, S=3)
    mma_gemm<64,3,true,false,true,false,true><<<dim3(FF_/64, NT/128, 1), blk, SM64_3>>>(
        xh, xl, C_, w1h, w1l, FF_, b1, nullptr, nullptr, h1h, h1l, FF_, C_, 0,0,0,0);
    // 9) y = x + h1 @ W2 + b2 (fp32 out, S=3, K=1024)
    mma_gemm<32,3,true,true,false,true,false><<<dim3(C_/32, NT/128, 1), blk, SM32_3>>>(
        h1h, h1l, FF_, w2h, w2l, C_, b2, xb, yb, nullptr, nullptr, C_, FF_, 0,0,0,0);
    // 10) out = LN2(y), 4 rows/CTA
    ln_kernel<false><<<NT/4, blk>>>(yb, ln2g, ln2b, out, nullptr, nullptr);
}

// round 15
// speedup vs baseline: 1.1084x; 1.0209x over previous
#include <cuda_runtime.h>
#include <cuda_bf16.h>
#include <math.h>
#include <cstdint>

// Problem constants
#define B_    8
#define KTOK  512
#define C_    256
#define HEADS 8
#define DH    32
#define NS    64
#define FF_   1024
#define NT    (B_*KTOK)   // 4096 tokens

// ---------------- scratch (device globals; no allocation allowed) ----------
__device__ float d_y [NT*C_];
__device__ float d_x [NT*C_];

__device__ __nv_bfloat16 d_wqh[C_*C_],  d_wql[C_*C_];
__device__ __nv_bfloat16 d_wvh[C_*C_],  d_wvl[C_*C_];
__device__ __nv_bfloat16 d_woh[C_*C_],  d_wol[C_*C_];
__device__ __nv_bfloat16 d_w1h[C_*FF_], d_w1l[C_*FF_];
__device__ __nv_bfloat16 d_w2h[FF_*C_], d_w2l[FF_*C_];
__device__ __nv_bfloat16 d_wkth[C_*C_], d_wktl[C_*C_];   // scale * Wk^T
__device__ __nv_bfloat16 d_qh [NT*C_],  d_ql [NT*C_];    // query
__device__ __nv_bfloat16 d_qkh[NT*HEADS*C_], d_qkl[NT*HEADS*C_];
__device__ __nv_bfloat16 d_gh [NT*HEADS*C_], d_gl [NT*HEADS*C_];
__device__ __nv_bfloat16 d_ch [NT*C_],  d_cl [NT*C_];
__device__ __nv_bfloat16 d_xh [NT*C_],  d_xl [NT*C_];
__device__ __nv_bfloat16 d_h1h[NT*FF_], d_h1l[NT*FF_];

__device__ __forceinline__ float gelu_tanh(float x) {
    float x3 = x*x*x;
    return 0.5f*x*(1.f + tanhf(0.7978845608028654f*(x + 0.044715f*x3)));
}

__device__ __forceinline__ uint32_t smem_u32(const void* p) {
    uint32_t a;
    asm("{ .reg .u64 t; cvta.to.shared.u64 t, %1; cvt.u32.u64 %0, t; }" : "=r"(a) : "l"(p));
    return a;
}

// ---- ldmatrix / mma.sync / cp.async wrappers (arch-agnostic, sm_80+) -------
__device__ __forceinline__ void ldsm_x4(uint32_t (&r)[4], uint32_t addr) {
    asm volatile("ldmatrix.sync.aligned.m8n8.x4.shared.b16 {%0,%1,%2,%3}, [%4];"
        : "=r"(r[0]), "=r"(r[1]), "=r"(r[2]), "=r"(r[3]) : "r"(addr));
}
__device__ __forceinline__ void ldsm_x4_t(uint32_t (&r)[4], uint32_t addr) {
    asm volatile("ldmatrix.sync.aligned.m8n8.x4.trans.shared.b16 {%0,%1,%2,%3}, [%4];"
        : "=r"(r[0]), "=r"(r[1]), "=r"(r[2]), "=r"(r[3]) : "r"(addr));
}
__device__ __forceinline__ void ldsm_x2(uint32_t (&r)[2], uint32_t addr) {
    asm volatile("ldmatrix.sync.aligned.m8n8.x2.shared.b16 {%0,%1}, [%2];"
        : "=r"(r[0]), "=r"(r[1]) : "r"(addr));
}
__device__ __forceinline__ void mma_bf16(float (&d)[4], const uint32_t (&a)[4],
                                         uint32_t b0, uint32_t b1) {
    asm volatile(
        "mma.sync.aligned.m16n8k16.row.col.f32.bf16.bf16.f32 "
        "{%0,%1,%2,%3}, {%4,%5,%6,%7}, {%8,%9}, {%0,%1,%2,%3};"
        : "+f"(d[0]), "+f"(d[1]), "+f"(d[2]), "+f"(d[3])
        : "r"(a[0]), "r"(a[1]), "r"(a[2]), "r"(a[3]), "r"(b0), "r"(b1));
}
__device__ __forceinline__ void cp16(uint32_t dst, const void* src) {
    asm volatile("cp.async.cg.shared.global [%0], [%1], 16;" :: "r"(dst), "l"(src));
}
#define CP_COMMIT() asm volatile("cp.async.commit_group;" ::: "memory")
#define CP_WAIT(n)  asm volatile("cp.async.wait_group %0;" :: "n"(n) : "memory")

// round-to-nearest hi/lo split (weights, outputs)
__device__ __forceinline__ void split2(float x, float y, uint32_t& h, uint32_t& l) {
    __nv_bfloat162 hh = __floats2bfloat162_rn(x, y);
    float rx = x - __bfloat162float(hh.x);
    float ry = y - __bfloat162float(hh.y);
    __nv_bfloat162 ll = __floats2bfloat162_rn(rx, ry);
    h = *(uint32_t*)&hh;  l = *(uint32_t*)&ll;
}
// truncation hi/lo split (cheaper; residual <= 2^-17 rel) — attn feats hot path
__device__ __forceinline__ void split2t(float x, float y, uint32_t& h, uint32_t& l) {
    uint32_t bx = __float_as_uint(x), by = __float_as_uint(y);
    h = (bx >> 16) | (by & 0xFFFF0000u);
    float lx = x - __uint_as_float(bx & 0xFFFF0000u);
    float ly = y - __uint_as_float(by & 0xFFFF0000u);
    __nv_bfloat162 ll = __floats2bfloat162_rn(lx, ly);
    l = *(uint32_t*)&ll;
}

// ---------------- single merged conversion kernel ----------------------------
__device__ __forceinline__ void seg_split(const float* __restrict__ in,
                                          __nv_bfloat16* __restrict__ oh,
                                          __nv_bfloat16* __restrict__ ol,
                                          int blk, int tid)
{
    int i = blk*256 + tid;
    float4 v = ((const float4*)in)[i];
    uint32_t h0, l0, h1, l1;
    split2(v.x, v.y, h0, l0);
    split2(v.z, v.w, h1, l1);
    ((uint2*)oh)[i] = make_uint2(h0, h1);
    ((uint2*)ol)[i] = make_uint2(l0, l1);
}

__global__ void conv_all(const float* __restrict__ query, const float* __restrict__ Wq,
                         const float* __restrict__ Wv, const float* __restrict__ Wo,
                         const float* __restrict__ W1, const float* __restrict__ W2,
                         const float* __restrict__ Wk,
                         __nv_bfloat16* qh, __nv_bfloat16* ql,
                         __nv_bfloat16* wqh, __nv_bfloat16* wql,
                         __nv_bfloat16* wvh, __nv_bfloat16* wvl,
                         __nv_bfloat16* woh, __nv_bfloat16* wol,
                         __nv_bfloat16* w1h, __nv_bfloat16* w1l,
                         __nv_bfloat16* w2h, __nv_bfloat16* w2l,
                         __nv_bfloat16* wkth, __nv_bfloat16* wktl)
{
    __shared__ float ts[64][65];
    const int bid = blockIdx.x, tid = threadIdx.x;
    if      (bid < 1024) seg_split(query, qh, ql, bid, tid);
    else if (bid < 1088) seg_split(Wq, wqh, wql, bid - 1024, tid);
    else if (bid < 1152) seg_split(Wv, wvh, wvl, bid - 1088, tid);
    else if (bid < 1216) seg_split(Wo, woh, wol, bid - 1152, tid);
    else if (bid < 1472) seg_split(W1, w1h, w1l, bid - 1216, tid);
    else if (bid < 1728) seg_split(W2, w2h, w2l, bid - 1472, tid);
    else {
        const int t = bid - 1728;
        const int tc = (t >> 2)*64, td = (t & 3)*64;
        #pragma unroll
        for (int j = 0; j < 4; j++) {
            int idx = tid + 256*j;
            int r = idx >> 4, q = idx & 15;
            float4 v = *(const float4*)&Wk[(size_t)(tc + r)*C_ + td + q*4];
            ts[r][q*4+0] = v.x; ts[r][q*4+1] = v.y;
            ts[r][q*4+2] = v.z; ts[r][q*4+3] = v.w;
        }
        __syncthreads();
        const float scale = 0.17677669529663687f;   // 1/sqrt(32)
        #pragma unroll
        for (int j = 0; j < 4; j++) {
            int idx = tid + 256*j;
            int r2 = idx >> 4, q2 = idx & 15;
            float v0 = ts[q2*4+0][r2]*scale, v1 = ts[q2*4+1][r2]*scale;
            float v2 = ts[q2*4+2][r2]*scale, v3 = ts[q2*4+3][r2]*scale;
            uint32_t h0, l0, h1, l1;
            split2(v0, v1, h0, l0);
            split2(v2, v3, h1, l1);
            size_t e = (size_t)(td + r2)*C_ + tc + q2*4;
            *(uint2*)&wkth[e] = make_uint2(h0, h1);
            *(uint2*)&wktl[e] = make_uint2(l0, l1);
        }
    }
}

// ======= bf16 hi/lo tensor-core GEMM, cp.async pipelined ====================
template<int TN, int S, bool BIAS, bool RES, bool GELU, bool OF32, bool OHL>
__global__ __launch_bounds__(256, 2)
void mma_gemm(const __nv_bfloat16* __restrict__ Ah, const __nv_bfloat16* __restrict__ Al,
              int lda,
              const __nv_bfloat16* __restrict__ Bh, const __nv_bfloat16* __restrict__ Bl,
              int ldw,
              const float* __restrict__ bias, const float* __restrict__ res,
              float* __restrict__ Out, __nv_bfloat16* __restrict__ OutH,
              __nv_bfloat16* __restrict__ OutL,
              int ldo, int K, int za, int zw, int zb, int zo)
{
    constexpr int AROW   = 80;
    constexpr int BROW   = TN*2 + 16;
    constexpr int A_BYTES = 128*AROW;
    constexpr int B_BYTES = 32*BROW;
    constexpr int STAGE  = 2*A_BYTES + 2*B_BYTES;
    constexpr int NB16   = TN/32;
    constexpr int BCH    = TN/8;
    constexpr int BCHT   = 32*BCH;

    extern __shared__ char smem[];
    const uint32_t sb = smem_u32(smem);
    const int tid  = threadIdx.x;
    const int lane = tid & 31, wid = tid >> 5;
    const int wm = wid & 3, wn = wid >> 2;
    const int m0 = blockIdx.y*128, n0 = blockIdx.x*TN;
    const int z = blockIdx.z;
    Ah += (size_t)z*za;  Al += (size_t)z*za;
    Bh += (size_t)z*zw;  Bl += (size_t)z*zw;
    if (OF32) Out += (size_t)z*zo;
    if (OHL) { OutH += (size_t)z*zo; OutL += (size_t)z*zo; }
    if (BIAS) bias += (size_t)z*zb;
    if (RES)  res  += (size_t)z*zo;

    float acc[2][NB16*2][4];
    #pragma unroll
    for (int a = 0; a < 2; a++)
        #pragma unroll
        for (int b = 0; b < NB16*2; b++)
            #pragma unroll
            for (int c = 0; c < 4; c++) acc[a][b][c] = 0.f;

    auto issue = [&](int chunk, int s) {
        const uint32_t sa = sb + s*STAGE;
        const int kc = chunk*32;
        #pragma unroll
        for (int j = 0; j < 2; j++) {
            int idx = tid + 256*j;
            int row = idx >> 2, ch = idx & 3;
            size_t soff = (size_t)(m0 + row)*lda + kc + ch*8;
            uint32_t d = sa + row*AROW + ch*16;
            cp16(d,           Ah + soff);
            cp16(d + A_BYTES, Al + soff);
        }
        if (BCHT >= 256) {
            #pragma unroll
            for (int j = 0; j < BCHT/256; j++) {
                int idx = tid + 256*j;
                int row = idx / BCH, ch = idx % BCH;
                size_t soff = (size_t)(kc + row)*ldw + n0 + ch*8;
                uint32_t d = sa + 2*A_BYTES + row*BROW + ch*16;
                cp16(d,           Bh + soff);
                cp16(d + B_BYTES, Bl + soff);
            }
        } else {
            if (tid < BCHT) {
                int row = tid / BCH, ch = tid % BCH;
                size_t soff = (size_t)(kc + row)*ldw + n0 + ch*8;
                uint32_t d = sa + 2*A_BYTES + row*BROW + ch*16;
                cp16(d,           Bh + soff);
                cp16(d + B_BYTES, Bl + soff);
            }
        }
    };
    auto compute = [&](int s) {
        const uint32_t a_h = sb + s*STAGE;
        const uint32_t a_l = a_h + A_BYTES;
        const uint32_t b_h = a_h + 2*A_BYTES;
        const uint32_t b_l = b_h + B_BYTES;
        const int l15 = lane & 15, l16 = lane >> 4;
        #pragma unroll
        for (int k16 = 0; k16 < 2; k16++) {
            uint32_t ah[2][4], al[2][4];
            #pragma unroll
            for (int mt = 0; mt < 2; mt++) {
                uint32_t aoff = (uint32_t)((wm*32 + mt*16 + l15)*AROW + k16*32 + l16*16);
                ldsm_x4(ah[mt], a_h + aoff);
                ldsm_x4(al[mt], a_l + aoff);
            }
            #pragma unroll
            for (int nb = 0; nb < NB16; nb++) {
                uint32_t boff = (uint32_t)((k16*16 + l15)*BROW + (wn*(TN/2) + nb*16)*2 + l16*16);
                uint32_t bh[4], bl[4];
                ldsm_x4_t(bh, b_h + boff);
                ldsm_x4_t(bl, b_l + boff);
                #pragma unroll
                for (int mt = 0; mt < 2; mt++) {
                    mma_bf16(acc[mt][nb*2],   ah[mt], bh[0], bh[1]);
                    mma_bf16(acc[mt][nb*2],   ah[mt], bl[0], bl[1]);
                    mma_bf16(acc[mt][nb*2],   al[mt], bh[0], bh[1]);
                    mma_bf16(acc[mt][nb*2+1], ah[mt], bh[2], bh[3]);
                    mma_bf16(acc[mt][nb*2+1], ah[mt], bl[2], bl[3]);
                    mma_bf16(acc[mt][nb*2+1], al[mt], bh[2], bh[3]);
                }
            }
        }
    };

    const int NC = K/32;
    #pragma unroll
    for (int s = 0; s < S - 1; s++) {
        if (s < NC) issue(s, s);
        CP_COMMIT();
    }
    for (int i = 0; i < NC; i++) {
        CP_WAIT(S - 2);
        __syncthreads();
        const int nx = i + S - 1;
        if (nx < NC) issue(nx, nx % S);
        CP_COMMIT();
        compute(i % S);
    }

    const int g = lane >> 2, tg = lane & 3;
    #pragma unroll
    for (int mt = 0; mt < 2; mt++) {
        const int r0 = m0 + wm*32 + mt*16 + g;
        #pragma unroll
        for (int j = 0; j < NB16*2; j++) {
            const int col = n0 + wn*(TN/2) + j*8 + tg*2;
            float v0 = acc[mt][j][0], v1 = acc[mt][j][1];
            float v2 = acc[mt][j][2], v3 = acc[mt][j][3];
            if (BIAS) {
                float b0 = bias[col], b1 = bias[col+1];
                v0 += b0; v1 += b1; v2 += b0; v3 += b1;
            }
            if (RES) {
                const float* rp0 = &res[(size_t)r0*ldo + col];
                const float* rp1 = &res[(size_t)(r0+8)*ldo + col];
                v0 += rp0[0]; v1 += rp0[1]; v2 += rp1[0]; v3 += rp1[1];
            }
            if (GELU) { v0 = gelu_tanh(v0); v1 = gelu_tanh(v1);
                        v2 = gelu_tanh(v2); v3 = gelu_tanh(v3); }
            if (OF32) {
                *(float2*)&Out[(size_t)r0*ldo + col]     = make_float2(v0, v1);
                *(float2*)&Out[(size_t)(r0+8)*ldo + col] = make_float2(v2, v3);
            }
            if (OHL) {
                uint32_t h0, l0, h1, l1;
                split2(v0, v1, h0, l0);
                split2(v2, v3, h1, l1);
                *(uint32_t*)&OutH[(size_t)r0*ldo + col]     = h0;
                *(uint32_t*)&OutL[(size_t)r0*ldo + col]     = l0;
                *(uint32_t*)&OutH[(size_t)(r0+8)*ldo + col] = h1;
                *(uint32_t*)&OutL[(size_t)(r0+8)*ldo + col] = l1;
            }
        }
    }
}

// ======= fused qp->qk kernel: qk_h = (query @ Wq_h + bq_h) @ (scale*Wk^T)_h ==
// grid (NT/128, HEADS). GEMM1: 128x32 K=256 (S=2 pipeline). Epilogue -> smem
// hi/lo qp tile. GEMM2: 128x256 K=32 vs wkt tile, two n-half passes.
#define FQ_AROW      80
#define FQ_A_BYTES   (128*FQ_AROW)                 // 10240
#define FQ_B1ROW     80
#define FQ_B1_BYTES  (32*FQ_B1ROW)                 // 2560
#define FQ_STAGE     (2*FQ_A_BYTES + 2*FQ_B1_BYTES) // 25600
#define FQ_QP        (2*FQ_STAGE)                  // 51200
#define FQ_WKT       (FQ_QP + 2*FQ_A_BYTES)        // 71680
#define FQ_WKTROW    528
#define FQ_WKT_BYTES (32*FQ_WKTROW)                // 16896
#define FQ_SMEM      (FQ_WKT + 2*FQ_WKT_BYTES)     // 105472

__global__ __launch_bounds__(256, 2)
void fused_qk(const __nv_bfloat16* __restrict__ qh, const __nv_bfloat16* __restrict__ ql,
              const __nv_bfloat16* __restrict__ wqh, const __nv_bfloat16* __restrict__ wql,
              const float* __restrict__ bq,
              const __nv_bfloat16* __restrict__ wkth, const __nv_bfloat16* __restrict__ wktl,
              __nv_bfloat16* __restrict__ qkh, __nv_bfloat16* __restrict__ qkl)
{
    extern __shared__ char smem[];
    const uint32_t sb = smem_u32(smem);
    const int tid = threadIdx.x, lane = tid & 31, wid = tid >> 5;
    const int wm = wid & 3, wn = wid >> 2;
    const int m0 = blockIdx.x*128;
    const int h  = blockIdx.y;
    const __nv_bfloat16* Bh = wqh + h*DH;
    const __nv_bfloat16* Bl = wql + h*DH;
    const __nv_bfloat16* Kh = wkth + (size_t)h*DH*C_;
    const __nv_bfloat16* Kl = wktl + (size_t)h*DH*C_;

    // issue wkt tile loads first (drained by the first CP_WAIT)
    #pragma unroll
    for (int j = 0; j < 4; j++) {
        int idx = tid + 256*j;
        int row = idx >> 5, ch = idx & 31;
        size_t soff = (size_t)row*C_ + ch*8;
        uint32_t d = sb + FQ_WKT + row*FQ_WKTROW + ch*16;
        cp16(d,                Kh + soff);
        cp16(d + FQ_WKT_BYTES, Kl + soff);
    }
    CP_COMMIT();

    auto issue1 = [&](int chunk, int s) {
        const uint32_t sa = sb + s*FQ_STAGE;
        const int kc = chunk*32;
        #pragma unroll
        for (int j = 0; j < 2; j++) {
            int idx = tid + 256*j;
            int row = idx >> 2, ch = idx & 3;
            size_t soff = (size_t)(m0 + row)*C_ + kc + ch*8;
            uint32_t d = sa + row*FQ_AROW + ch*16;
            cp16(d,              qh + soff);
            cp16(d + FQ_A_BYTES, ql + soff);
        }
        if (tid < 128) {
            int row = tid >> 2, ch = tid & 3;
            size_t soff = (size_t)(kc + row)*C_ + ch*8;
            uint32_t d = sa + 2*FQ_A_BYTES + row*FQ_B1ROW + ch*16;
            cp16(d,               Bh + soff);
            cp16(d + FQ_B1_BYTES, Bl + soff);
        }
    };

    float acc[2][2][4];
    #pragma unroll
    for (int a = 0; a < 2; a++)
        #pragma unroll
        for (int b = 0; b < 2; b++)
            #pragma unroll
            for (int c = 0; c < 4; c++) acc[a][b][c] = 0.f;

    auto compute1 = [&](int s) {
        const uint32_t a_h = sb + s*FQ_STAGE;
        const uint32_t a_l = a_h + FQ_A_BYTES;
        const uint32_t b_h = a_h + 2*FQ_A_BYTES;
        const uint32_t b_l = b_h + FQ_B1_BYTES;
        const int l15 = lane & 15, l16 = lane >> 4;
        #pragma unroll
        for (int k16 = 0; k16 < 2; k16++) {
            uint32_t ah[2][4], al[2][4];
            #pragma unroll
            for (int mt = 0; mt < 2; mt++) {
                uint32_t aoff = (uint32_t)((wm*32 + mt*16 + l15)*FQ_AROW + k16*32 + l16*16);
                ldsm_x4(ah[mt], a_h + aoff);
                ldsm_x4(al[mt], a_l + aoff);
            }
            uint32_t boff = (uint32_t)((k16*16 + l15)*FQ_B1ROW + wn*32 + l16*16);
            uint32_t bh4[4], bl4[4];
            ldsm_x4_t(bh4, b_h + boff);
            ldsm_x4_t(bl4, b_l + boff);
            #pragma unroll
            for (int mt = 0; mt < 2; mt++) {
                mma_bf16(acc[mt][0], ah[mt], bh4[0], bh4[1]);
                mma_bf16(acc[mt][0], ah[mt], bl4[0], bl4[1]);
                mma_bf16(acc[mt][0], al[mt], bh4[0], bh4[1]);
                mma_bf16(acc[mt][1], ah[mt], bh4[2], bh4[3]);
                mma_bf16(acc[mt][1], ah[mt], bl4[2], bl4[3]);
                mma_bf16(acc[mt][1], al[mt], bh4[2], bh4[3]);
            }
        }
    };

    // GEMM1 mainloop (S=2, NC=8)
    issue1(0, 0);
    CP_COMMIT();
    for (int i = 0; i < 8; i++) {
        CP_WAIT(0);
        __syncthreads();
        if (i + 1 < 8) issue1(i + 1, (i + 1) & 1);
        CP_COMMIT();
        compute1(i & 1);
    }

    // epilogue1: +bq, hi/lo split -> QP smem tile (80B pitch)
    {
        const int g = lane >> 2, tg = lane & 3;
        #pragma unroll
        for (int mt = 0; mt < 2; mt++) {
            int r0 = wm*32 + mt*16 + g;
            #pragma unroll
            for (int j = 0; j < 2; j++) {
                int col = wn*16 + j*8 + tg*2;
                float b0 = bq[h*DH + col], b1 = bq[h*DH + col + 1];
                float v0 = acc[mt][j][0] + b0, v1 = acc[mt][j][1] + b1;
                float v2 = acc[mt][j][2] + b0, v3 = acc[mt][j][3] + b1;
                uint32_t h0, l0, h1, l1;
                split2(v0, v1, h0, l0);
                split2(v2, v3, h1, l1);
                *(uint32_t*)(smem + FQ_QP + r0*FQ_AROW + col*2)                    = h0;
                *(uint32_t*)(smem + FQ_QP + FQ_A_BYTES + r0*FQ_AROW + col*2)       = l0;
                *(uint32_t*)(smem + FQ_QP + (r0+8)*FQ_AROW + col*2)                = h1;
                *(uint32_t*)(smem + FQ_QP + FQ_A_BYTES + (r0+8)*FQ_AROW + col*2)   = l1;
            }
        }
    }
    __syncthreads();

    // GEMM2: qk[128,256] = qp[128,32] @ wkt[32,256]
    // Two n-half passes; per pass each warp covers 64 cols (4m x 2n layout).
    const uint32_t qp_h = sb + FQ_QP;
    const uint32_t qp_l = qp_h + FQ_A_BYTES;
    const uint32_t wk_h = sb + FQ_WKT;
    const uint32_t wk_l = wk_h + FQ_WKT_BYTES;
    const int l15 = lane & 15, l16 = lane >> 4;
    #pragma unroll
    for (int nh = 0; nh < 2; nh++) {
        const int nbase = nh*128 + wn*64;
        float a2[2][8][4];
        #pragma unroll
        for (int a = 0; a < 2; a++)
            #pragma unroll
            for (int b = 0; b < 8; b++)
                #pragma unroll
                for (int c = 0; c < 4; c++) a2[a][b][c] = 0.f;
        #pragma unroll
        for (int k16 = 0; k16 < 2; k16++) {
            uint32_t ah[2][4], al[2][4];
            #pragma unroll
            for (int mt = 0; mt < 2; mt++) {
                uint32_t aoff = (uint32_t)((wm*32 + mt*16 + l15)*FQ_AROW + k16*32 + l16*16);
                ldsm_x4(ah[mt], qp_h + aoff);
                ldsm_x4(al[mt], qp_l + aoff);
            }
            #pragma unroll
            for (int nb = 0; nb < 4; nb++) {
                uint32_t boff = (uint32_t)((k16*16 + l15)*FQ_WKTROW + (nbase + nb*16)*2 + l16*16);
                uint32_t bh4[4], bl4[4];
                ldsm_x4_t(bh4, wk_h + boff);
                ldsm_x4_t(bl4, wk_l + boff);
                #pragma unroll
                for (int mt = 0; mt < 2; mt++) {
                    mma_bf16(a2[mt][nb*2],   ah[mt], bh4[0], bh4[1]);
                    mma_bf16(a2[mt][nb*2],   ah[mt], bl4[0], bl4[1]);
                    mma_bf16(a2[mt][nb*2],   al[mt], bh4[0], bh4[1]);
                    mma_bf16(a2[mt][nb*2+1], ah[mt], bh4[2], bh4[3]);
                    mma_bf16(a2[mt][nb*2+1], ah[mt], bl4[2], bl4[3]);
                    mma_bf16(a2[mt][nb*2+1], al[mt], bh4[2], bh4[3]);
                }
            }
        }
        // epilogue2: write qk hi/lo at [tok, h, col]
        const int g = lane >> 2, tg = lane & 3;
        #pragma unroll
        for (int mt = 0; mt < 2; mt++) {
            const size_t r0 = (size_t)(m0 + wm*32 + mt*16 + g);
            #pragma unroll
            for (int j = 0; j < 8; j++) {
                int col = nbase + j*8 + tg*2;
                uint32_t h0, l0, h1, l1;
                split2(a2[mt][j][0], a2[mt][j][1], h0, l0);
                split2(a2[mt][j][2], a2[mt][j][3], h1, l1);
                size_t e0 = r0*(HEADS*C_) + (size_t)h*C_ + col;
                size_t e1 = (r0+8)*(HEADS*C_) + (size_t)h*C_ + col;
                *(uint32_t*)&qkh[e0] = h0;
                *(uint32_t*)&qkl[e0] = l0;
                *(uint32_t*)&qkh[e1] = h1;
                *(uint32_t*)&qkl[e1] = l1;
            }
        }
    }
}

// ---- bilinear tap of the 9x9 rel-pos table ---------------------------------
__device__ __forceinline__ float bil_corner(const float* __restrict__ th,
                                            int yi, int xi, float w)
{
    if (xi < 0 || xi > 8 || yi < 0 || yi > 8) return 0.f;
    return th[yi*9 + xi]*w;
}
__device__ __forceinline__ float grid_bias(const float* __restrict__ sp,
                                           const float* __restrict__ tab,
                                           int h, int n)
{
    float gx = (sp[2*n]   + 1.f)*4.f;
    float gy = (sp[2*n+1] + 1.f)*4.f;
    float x0f = floorf(gx), y0f = floorf(gy);
    int   x0 = (int)x0f,    y0 = (int)y0f;
    float wx1 = gx - x0f, wx0 = 1.f - wx1;
    float wy1 = gy - y0f, wy0 = 1.f - wy1;
    const float* th = &tab[h*81];
    return bil_corner(th, y0,   x0,   wy0*wx0)
         + bil_corner(th, y0,   x0+1, wy0*wx1)
         + bil_corner(th, y0+1, x0,   wy1*wx0)
         + bil_corner(th, y0+1, x0+1, wy1*wx1);
}

// ---------------- fused local attention v7 (round-13 best) ------------------
#define ASM_FH   0
#define ASM_FL   36864
#define ASM_PH   73728
#define ASM_PL   74880
#define ASM_SP   76032
#define ASM_TAB  76544
#define ASM_QH   79168
#define ASM_QL   83392
#define ASM_SCP  87616
#define ATTN_SMEM_BYTES 92736
#define FPITCH 144
#define QPITCH 528
#define PPITCH 144

__global__ __launch_bounds__(256, 2)
void attn_kernel(const float* __restrict__ lf,   const float* __restrict__ spat,
                 const float* __restrict__ table,
                 const __nv_bfloat16* __restrict__ qkh,
                 const __nv_bfloat16* __restrict__ qkl,
                 __nv_bfloat16* __restrict__ gh, __nv_bfloat16* __restrict__ gl)
{
    extern __shared__ char smem[];
    float* scp = (float*)(smem + ASM_SCP);
    float* sp  = (float*)(smem + ASM_SP);
    float* tab = (float*)(smem + ASM_TAB);
    const uint32_t sb = smem_u32(smem);

    const int tid  = threadIdx.x;
    const int lane = tid & 31, w = tid >> 5;
    const int gid  = tid >> 7, lt = tid & 127;
    const int bk = blockIdx.x;
    const int b  = bk >> 9, k = bk & 511;

    const float* lfb = lf + (size_t)b*(C_*KTOK*NS) + (size_t)k*NS;
    const int v = lt & 15, cg = lt >> 4;
    float4 f[16];
    #pragma unroll
    for (int rr = 0; rr < 16; rr++) {
        int c = gid*128 + rr*8 + cg;
        f[rr] = *(const float4*)(lfb + (size_t)c*(KTOK*NS) + v*4);
    }
    {
        const uint2* qh4 = (const uint2*)(qkh + (size_t)bk*2048);
        const uint2* ql4 = (const uint2*)(qkl + (size_t)bk*2048);
        #pragma unroll
        for (int jj = 0; jj < 2; jj++) {
            int idx = lt + 128*jj;
            int h = idx >> 5, c32 = idx & 31;
            int gidx = h*64 + gid*32 + c32;
            uint2 vh = qh4[gidx], vl = ql4[gidx];
            uint32_t off = h*QPITCH + (gid*128 + c32*4)*2;
            *(uint2*)(smem + ASM_QH + off) = vh;
            *(uint2*)(smem + ASM_QL + off) = vl;
        }
    }
    if (tid < 128) sp[tid] = spat[(size_t)bk*128 + tid];
    for (int j = tid; j < 648; j += 256) tab[j] = table[j];

    #pragma unroll
    for (int rr = 0; rr < 16; rr++) {
        int c = gid*128 + rr*8 + cg;
        uint32_t h0, l0, h1, l1;
        split2t(f[rr].x, f[rr].y, h0, l0);
        split2t(f[rr].z, f[rr].w, h1, l1);
        uint32_t off = c*FPITCH + v*8;
        *(uint2*)(smem + ASM_FH + off) = make_uint2(h0, h1);
        *(uint2*)(smem + ASM_FL + off) = make_uint2(l0, l1);
    }
    asm volatile("bar.sync %0, 128;" :: "r"(1 + gid) : "memory");

    // phase 1: two independent accumulator chains
    {
        const int mt = w & 3, kh = gid;
        const int l15 = lane & 15;
        float dA[4] = {0.f,0.f,0.f,0.f}, dB[4] = {0.f,0.f,0.f,0.f};
        const uint32_t bBase = sb + ASM_QH +
            (uint32_t)((lane & 7)*QPITCH + ((lane >> 3) & 1)*16);
        #pragma unroll
        for (int kk = 0; kk < 8; kk += 2) {
            #pragma unroll
            for (int p = 0; p < 2; p++) {
                const int k16 = kh*8 + kk + p;
                uint32_t aaddr = sb + ASM_FH +
                    (uint32_t)((k16*16 + l15)*FPITCH + mt*32 + (lane >> 4)*16);
                uint32_t r0[4], r1[4];
                ldsm_x4_t(r0, aaddr);
                ldsm_x4_t(r1, aaddr + (ASM_FL - ASM_FH));
                uint32_t ah[4] = { r0[0], r0[2], r0[1], r0[3] };
                uint32_t al[4] = { r1[0], r1[2], r1[1], r1[3] };
                uint32_t bh[2], bl[2];
                ldsm_x2(bh, bBase + k16*32);
                ldsm_x2(bl, bBase + k16*32 + (ASM_QL - ASM_QH));
                if (p == 0) {
                    mma_bf16(dA, ah, bh[0], bh[1]);
                    mma_bf16(dA, ah, bl[0], bl[1]);
                    mma_bf16(dA, al, bh[0], bh[1]);
                } else {
                    mma_bf16(dB, ah, bh[0], bh[1]);
                    mma_bf16(dB, ah, bl[0], bl[1]);
                    mma_bf16(dB, al, bh[0], bh[1]);
                }
            }
        }
        const int g = lane >> 2, tg = lane & 3;
        float* dst = scp + kh*640;
        *(float2*)&dst[(mt*16 + g)*10 + tg*2]     = make_float2(dA[0]+dB[0], dA[1]+dB[1]);
        *(float2*)&dst[(mt*16 + g + 8)*10 + tg*2] = make_float2(dA[2]+dB[2], dA[3]+dB[3]);
    }
    __syncthreads();

    // combine + bias + softmax
    {
        int n0 = lane, n1 = lane + 32;
        float v0 = scp[n0*10 + w] + scp[640 + n0*10 + w] + grid_bias(sp, tab, w, n0);
        float v1 = scp[n1*10 + w] + scp[640 + n1*10 + w] + grid_bias(sp, tab, w, n1);
        float m = fmaxf(v0, v1);
        #pragma unroll
        for (int o = 16; o > 0; o >>= 1) m = fmaxf(m, __shfl_xor_sync(0xffffffffu, m, o));
        float e0 = expf(v0 - m), e1 = expf(v1 - m);
        float s = e0 + e1;
        #pragma unroll
        for (int o = 16; o > 0; o >>= 1) s += __shfl_xor_sync(0xffffffffu, s, o);
        float inv = 1.f/s;
        float p0 = e0*inv, p1 = e1*inv;
        __nv_bfloat16 h0 = __float2bfloat16_rn(p0);
        __nv_bfloat16 l0 = __float2bfloat16_rn(p0 - __bfloat162float(h0));
        __nv_bfloat16 h1 = __float2bfloat16_rn(p1);
        __nv_bfloat16 l1 = __float2bfloat16_rn(p1 - __bfloat162float(h1));
        *(__nv_bfloat16*)(smem + ASM_PH + w*PPITCH + lane*2)      = h0;
        *(__nv_bfloat16*)(smem + ASM_PL + w*PPITCH + lane*2)      = l0;
        *(__nv_bfloat16*)(smem + ASM_PH + w*PPITCH + (lane+32)*2) = h1;
        *(__nv_bfloat16*)(smem + ASM_PL + w*PPITCH + (lane+32)*2) = l1;
    }
    __syncthreads();

    // phase 2: four independent accumulator chains, direct hi/lo stores
    {
        const int l15 = lane & 15, l16 = lane >> 4;
        float d0a[4] = {0.f,0.f,0.f,0.f}, d0b[4] = {0.f,0.f,0.f,0.f};
        float d1a[4] = {0.f,0.f,0.f,0.f}, d1b[4] = {0.f,0.f,0.f,0.f};
        const uint32_t bBase = sb + ASM_PH +
            (uint32_t)((lane & 7)*PPITCH + ((lane >> 3) & 1)*16);
        #pragma unroll
        for (int k16 = 0; k16 < 4; k16++) {
            uint32_t bh[2], bl[2];
            ldsm_x2(bh, bBase + k16*32);
            ldsm_x2(bl, bBase + k16*32 + (ASM_PL - ASM_PH));
            uint32_t a0h[4], a0l[4], a1h[4], a1l[4];
            uint32_t aoff0 = sb + ASM_FH +
                (uint32_t)((w*16 + l15)*FPITCH + k16*32 + l16*16);
            uint32_t aoff1 = aoff0 + (uint32_t)(128*FPITCH);
            ldsm_x4(a0h, aoff0);
            ldsm_x4(a0l, aoff0 + (ASM_FL - ASM_FH));
            ldsm_x4(a1h, aoff1);
            ldsm_x4(a1l, aoff1 + (ASM_FL - ASM_FH));
            if (k16 & 1) {
                mma_bf16(d0b, a0h, bh[0], bh[1]);
                mma_bf16(d0b, a0h, bl[0], bl[1]);
                mma_bf16(d0b, a0l, bh[0], bh[1]);
                mma_bf16(d1b, a1h, bh[0], bh[1]);
                mma_bf16(d1b, a1h, bl[0], bl[1]);
                mma_bf16(d1b, a1l, bh[0], bh[1]);
            } else {
                mma_bf16(d0a, a0h, bh[0], bh[1]);
                mma_bf16(d0a, a0h, bl[0], bl[1]);
                mma_bf16(d0a, a0l, bh[0], bh[1]);
                mma_bf16(d1a, a1h, bh[0], bh[1]);
                mma_bf16(d1a, a1h, bl[0], bl[1]);
                mma_bf16(d1a, a1l, bh[0], bh[1]);
            }
        }
        const int g = lane >> 2, tg = lane & 3;
        const size_t tokb = (size_t)bk*HEADS*C_;
        auto stg = [&](int c, int h, float val) {
            __nv_bfloat16 hb = __float2bfloat16_rn(val);
            __nv_bfloat16 lb = __float2bfloat16_rn(val - __bfloat162float(hb));
            gh[tokb + (size_t)h*C_ + c] = hb;
            gl[tokb + (size_t)h*C_ + c] = lb;
        };
        int c0 = w*16 + g, c1 = (w+8)*16 + g;
        int h0 = 2*tg, h1 = 2*tg + 1;
        stg(c0,     h0, d0a[0]+d0b[0]);  stg(c0,     h1, d0a[1]+d0b[1]);
        stg(c0 + 8, h0, d0a[2]+d0b[2]);  stg(c0 + 8, h1, d0a[3]+d0b[3]);
        stg(c1,     h0, d1a[0]+d1b[0]);  stg(c1,     h1, d1a[1]+d1b[1]);
        stg(c1 + 8, h0, d1a[2]+d1b[2]);  stg(c1 + 8, h1, d1a[3]+d1b[3]);
    }
}

// ---------------- LayerNorm over C=256, 4 rows/CTA, float4/thread -----------
template<bool HL>
__global__ void ln_kernel(const float* __restrict__ in, const float* __restrict__ gw,
                          const float* __restrict__ bw, float* __restrict__ out,
                          __nv_bfloat16* __restrict__ oh, __nv_bfloat16* __restrict__ ol)
{
    const int tid = threadIdx.x;
    const int rg = tid >> 6;
    const int lt = tid & 63;
    const int row = blockIdx.x*4 + rg;
    const int wid = tid >> 5, lane = tid & 31;

    float4 v = ((const float4*)(in + (size_t)row*C_))[lt];
    float s  = v.x + v.y + v.z + v.w;
    float ss = v.x*v.x + v.y*v.y + v.z*v.z + v.w*v.w;
    #pragma unroll
    for (int o = 16; o > 0; o >>= 1) {
        s  += __shfl_xor_sync(0xffffffffu, s,  o);
        ss += __shfl_xor_sync(0xffffffffu, ss, o);
    }
    __shared__ float rs[8], rss[8];
    if (lane == 0) { rs[wid] = s; rss[wid] = ss; }
    __syncthreads();
    float S  = rs[rg*2]  + rs[rg*2 + 1];
    float SS = rss[rg*2] + rss[rg*2 + 1];
    float mu  = S*(1.f/C_);
    float var = SS*(1.f/C_) - mu*mu;
    float inv = rsqrtf(var + 1e-5f);

    float4 g4 = ((const float4*)gw)[lt];
    float4 b4 = ((const float4*)bw)[lt];
    float r0 = (v.x - mu)*inv*g4.x + b4.x;
    float r1 = (v.y - mu)*inv*g4.y + b4.y;
    float r2 = (v.z - mu)*inv*g4.z + b4.z;
    float r3 = (v.w - mu)*inv*g4.w + b4.w;
    ((float4*)(out + (size_t)row*C_))[lt] = make_float4(r0, r1, r2, r3);
    if (HL) {
        uint32_t h0, l0, h1, l1;
        split2(r0, r1, h0, l0);
        split2(r2, r3, h1, l1);
        ((uint2*)(oh + (size_t)row*C_))[lt] = make_uint2(h0, h1);
        ((uint2*)(ol + (size_t)row*C_))[lt] = make_uint2(l0, l1);
    }
}

// ---------------------------------------------------------------------------
extern "C" void kernel_launch(void* const* d_in, const int* in_sizes, int n_in,
                              void* d_out, int out_size)
{
    const float* query = (const float*)d_in[0];
    const float* lf    = (const float*)d_in[1];
    const float* spat  = (const float*)d_in[2];
    const float* table = (const float*)d_in[3];
    const float* Wq    = (const float*)d_in[4];
    const float* bq    = (const float*)d_in[5];
    const float* Wk    = (const float*)d_in[6];
    // d_in[7] = bk: constant over n -> cancels in softmax
    const float* Wv    = (const float*)d_in[8];
    const float* bv    = (const float*)d_in[9];
    const float* Wo    = (const float*)d_in[10];
    const float* bo    = (const float*)d_in[11];
    const float* ln1g  = (const float*)d_in[12];
    const float* ln1b  = (const float*)d_in[13];
    const float* W1    = (const float*)d_in[14];
    const float* b1    = (const float*)d_in[15];
    const float* W2    = (const float*)d_in[16];
    const float* b2    = (const float*)d_in[17];
    const float* ln2g  = (const float*)d_in[18];
    const float* ln2b  = (const float*)d_in[19];
    float* out = (float*)d_out;

    float *yb, *xb;
    cudaGetSymbolAddress((void**)&yb, d_y);
    cudaGetSymbolAddress((void**)&xb, d_x);

    __nv_bfloat16 *wqh,*wql,*wvh,*wvl,*woh,*wol,*w1h,*w1l,*w2h,*w2l,*wkth,*wktl;
    __nv_bfloat16 *qh,*ql,*qkh,*qkl,*gh,*gl,*ch,*cl,*xh,*xl,*h1h,*h1l;
    cudaGetSymbolAddress((void**)&wqh, d_wqh); cudaGetSymbolAddress((void**)&wql, d_wql);
    cudaGetSymbolAddress((void**)&wvh, d_wvh); cudaGetSymbolAddress((void**)&wvl, d_wvl);
    cudaGetSymbolAddress((void**)&woh, d_woh); cudaGetSymbolAddress((void**)&wol, d_wol);
    cudaGetSymbolAddress((void**)&w1h, d_w1h); cudaGetSymbolAddress((void**)&w1l, d_w1l);
    cudaGetSymbolAddress((void**)&w2h, d_w2h); cudaGetSymbolAddress((void**)&w2l, d_w2l);
    cudaGetSymbolAddress((void**)&wkth, d_wkth); cudaGetSymbolAddress((void**)&wktl, d_wktl);
    cudaGetSymbolAddress((void**)&qh,  d_qh);  cudaGetSymbolAddress((void**)&ql,  d_ql);
    cudaGetSymbolAddress((void**)&qkh, d_qkh); cudaGetSymbolAddress((void**)&qkl, d_qkl);
    cudaGetSymbolAddress((void**)&gh,  d_gh);  cudaGetSymbolAddress((void**)&gl,  d_gl);
    cudaGetSymbolAddress((void**)&ch,  d_ch);  cudaGetSymbolAddress((void**)&cl,  d_cl);
    cudaGetSymbolAddress((void**)&xh,  d_xh);  cudaGetSymbolAddress((void**)&xl,  d_xl);
    cudaGetSymbolAddress((void**)&h1h, d_h1h); cudaGetSymbolAddress((void**)&h1l, d_h1l);

    cudaFuncSetAttribute(attn_kernel, cudaFuncAttributeMaxDynamicSharedMemorySize,
                         ATTN_SMEM_BYTES);
    cudaFuncSetAttribute(fused_qk, cudaFuncAttributeMaxDynamicSharedMemorySize,
                         FQ_SMEM);

    const int SM64_3 = 3*(2*128*80 + 2*32*144);   // 89088
    const int SM32_3 = 3*(2*128*80 + 2*32*80);    // 76800
    cudaFuncSetAttribute((const void*)mma_gemm<32,3,true,false,false,false,true>,
                         cudaFuncAttributeMaxDynamicSharedMemorySize, SM32_3);
    cudaFuncSetAttribute((const void*)mma_gemm<32,3,true,true,false,true,false>,
                         cudaFuncAttributeMaxDynamicSharedMemorySize, SM32_3);
    cudaFuncSetAttribute((const void*)mma_gemm<64,3,true,false,true,false,true>,
                         cudaFuncAttributeMaxDynamicSharedMemorySize, SM64_3);

    dim3 blk(256);

    // 1) merged conversion kernel (weights + query + scale*Wk^T)
    conv_all<<<1744, blk>>>(query, Wq, Wv, Wo, W1, W2, Wk,
                            qh, ql, wqh, wql, wvh, wvl, woh, wol,
                            w1h, w1l, w2h, w2l, wkth, wktl);
    // 2) fused qp->qk (per-head, grid (32, 8))
    fused_qk<<<dim3(NT/128, HEADS), blk, FQ_SMEM>>>(
        qh, ql, wqh, wql, bq, wkth, wktl, qkh, qkl);
    // 3) fused local attention v7 -> g (bf16 hi/lo)
    attn_kernel<<<NT, blk, ATTN_SMEM_BYTES>>>(lf, spat, table, qkh, qkl, gh, gl);
    // 4) ctx = g @ Wv_h + bv (8 head-batched, hi/lo out, S=3)
    mma_gemm<32,3,true,false,false,false,true><<<dim3(1, NT/128, HEADS), blk, SM32_3>>>(
        gh, gl, HEADS*C_, wvh, wvl, C_, bv, nullptr, nullptr, ch, cl, C_, C_,
        /*za=*/C_, /*zw=*/DH, /*zb=*/DH, /*zo=*/DH);
    // 5) y = query + ctx @ Wo + bo (fp32 out, S=3)
    mma_gemm<32,3,true,true,false,true,false><<<dim3(C_/32, NT/128, 1), blk, SM32_3>>>(
        ch, cl, C_, woh, wol, C_, bo, query, yb, nullptr, nullptr, C_, C_, 0,0,0,0);
    // 6) x = LN1(y) (fp32 + hi/lo), 4 rows/CTA
    ln_kernel<true><<<NT/4, blk>>>(yb, ln1g, ln1b, xb, xh, xl);
    // 7) h1 = gelu(x @ W1 + b1) (hi/lo out, S=3)
    mma_gemm<64,3,true,false,true,false,true><<<dim3(FF_/64, NT/128, 1), blk, SM64_3>>>(
        xh, xl, C_, w1h, w1l, FF_, b1, nullptr, nullptr, h1h, h1l, FF_, C_, 0,0,0,0);
    // 8) y = x + h1 @ W2 + b2 (fp32 out, S=3, K=1024)
    mma_gemm<32,3,true,true,false,true,false><<<dim3(C_/32, NT/128, 1), blk, SM32_3>>>(
        h1h, h1l, FF_, w2h, w2l, C_, b2, xb, yb, nullptr, nullptr, C_, FF_, 0,0,0,0);
    // 9) out = LN2(y), 4 rows/CTA
    ln_kernel<false><<<NT/4, blk>>>(yb, ln2g, ln2b, out, nullptr, nullptr);
}